// round 2
// baseline (speedup 1.0000x reference)
#include <cuda_runtime.h>
#include <math.h>

#define DD 128
#define MAXN 50000
#define MAXE 800000

// Scratch (static __device__ — no allocations allowed)
__device__ float g_P[MAXN * DD];    // A @ h_n
__device__ float g_Q[MAXN * DD];    // B @ h_n + b1
__device__ float g_agg[MAXN * DD];  // scatter-add target
__device__ float g_t[MAXN * DD];    // silu(U1 @ [h;agg] + c1)
__device__ int   g_eidx[2 * MAXE];  // normalized int32 edge index
__device__ int   g_is64;            // dtype probe result

// silu(x) = x * sigmoid(x) = 0.5x * (1 + tanh(0.5x))  -> 1 MUFU + 2 FMA
__device__ __forceinline__ float fast_silu(float x) {
    float hx = 0.5f * x, t;
    asm("tanh.approx.f32 %0, %1;" : "=f"(t) : "f"(hx));
    return fmaf(hx, t, hx);
}

// ---------------------------------------------------------------------------
// Kernel 0a: probe edge_index dtype. int64 values < N have zero high words;
// int32 data puts random indices in those slots (cannot all be zero).
// ---------------------------------------------------------------------------
__global__ void k_detect(const unsigned int* __restrict__ p) {
    if (threadIdx.x == 0) {
        int is64 = 1;
        for (int i = 0; i < 512; i++)
            if (p[2 * i + 1] != 0u) { is64 = 0; break; }
        g_is64 = is64;
    }
}

// Kernel 0b: normalize edge_index -> int32, clamped to [0, N)
__global__ __launch_bounds__(256) void k_conv(const void* __restrict__ ei,
                                              int twoE, int N) {
    int i = blockIdx.x * blockDim.x + threadIdx.x;
    if (i >= twoE) return;
    long long v = g_is64 ? ((const long long*)ei)[i]
                         : (long long)((const int*)ei)[i];
    if (v < 0) v = 0;
    if (v >= N) v = N - 1;
    g_eidx[i] = (int)v;
}

// ---------------------------------------------------------------------------
// Kernel 1: P[n] = A @ h[n], Q[n] = B @ h[n] + b1, where W1 = [A | B | w_d]
// One block per 32-node tile. 256 threads. C tile = 256 outs x 32 nodes.
// ---------------------------------------------------------------------------
__global__ __launch_bounds__(256) void k_pq(const float* __restrict__ h,
                                            const float* __restrict__ W1,
                                            const float* __restrict__ b1, int N) {
    extern __shared__ float sm[];
    float* Ws = sm;             // [256][129]
    float* Xs = sm + 256 * 129; // [128][33]
    const int t = threadIdx.x;

    for (int idx = t; idx < 256 * DD; idx += 256) {
        int d = idx >> 7, k = idx & 127;
        Ws[d * 129 + k] = (d < DD) ? W1[d * 257 + k] : W1[(d - DD) * 257 + DD + k];
    }
    const int l = t & 31, w = t >> 5;
    const int n0 = blockIdx.x * 32;
    for (int r = w; r < 32; r += 8) {
        int node = n0 + r;
        for (int k = l; k < DD; k += 32)
            Xs[k * 33 + r] = (node < N) ? h[(size_t)node * DD + k] : 0.f;
    }
    __syncthreads();

    const int dg = t >> 3, ng = t & 7; // dg: 0..31 (8 outs each), ng: 0..7 (4 nodes each)
    float acc[8][4] = {};
#pragma unroll 8
    for (int k = 0; k < DD; k++) {
        float xv[4];
#pragma unroll
        for (int j = 0; j < 4; j++) xv[j] = Xs[k * 33 + ng * 4 + j];
#pragma unroll
        for (int i = 0; i < 8; i++) {
            float wv = Ws[(dg * 8 + i) * 129 + k];
#pragma unroll
            for (int j = 0; j < 4; j++) acc[i][j] = fmaf(wv, xv[j], acc[i][j]);
        }
    }
#pragma unroll
    for (int j = 0; j < 4; j++) {
        int node = n0 + ng * 4 + j;
        if (node >= N) continue;
#pragma unroll
        for (int i = 0; i < 8; i++) {
            int d = dg * 8 + i;
            if (d < DD) g_P[(size_t)node * DD + d] = acc[i][j];
            else        g_Q[(size_t)node * DD + (d - DD)] = acc[i][j] + b1[d - DD];
        }
    }
}

// ---------------------------------------------------------------------------
// Kernel 2 (edge): per 32-edge tile:
//   x = silu(P[s] + Q[r] + dist * w_d)          (stage 1, per-thread d)
//   m = silu(W2 @ x + b2)                        (smem GEMM)
//   atomicAdd into g_agg[r]                      (epilogue)
// Persistent-ish blocks so W2 smem load amortizes. 128 threads, 2 blocks/SM.
// ---------------------------------------------------------------------------
__global__ __launch_bounds__(128, 2) void k_edge(const float* __restrict__ coords,
                                                 const float* __restrict__ W1,
                                                 const float* __restrict__ W2,
                                                 const float* __restrict__ b2, int E) {
    extern __shared__ float sm[];
    float* Ws = sm;                  // [128][129]
    float* Xs = sm + 128 * 129;      // [128][33]
    float* sdist = Xs + 128 * 33;    // [32]
    int* ss = (int*)(sdist + 32);    // [32]
    int* sr = ss + 32;               // [32]
    const int t = threadIdx.x;

    for (int idx = t; idx < DD * DD; idx += 128) {
        int d = idx >> 7, k = idx & 127;
        Ws[d * 129 + k] = W2[idx];
    }
    const float wd = W1[t * 257 + 256]; // w_d column, d = t
    const int dg = t >> 3, ng = t & 7;
    float b2r[8];
#pragma unroll
    for (int i = 0; i < 8; i++) b2r[i] = b2[dg * 8 + i];

    const int numTiles = (E + 31) >> 5;
    for (int tile = blockIdx.x; tile < numTiles; tile += gridDim.x) {
        const int e0 = tile << 5;
        __syncthreads(); // protect smem vs previous iteration's readers
        if (t < 32) {
            int e = e0 + t;
            int s = 0, r = 0;
            float dist = 0.f;
            if (e < E) {
                s = g_eidx[e];
                r = g_eidx[E + e];
                float dx = coords[s * 3 + 0] - coords[r * 3 + 0];
                float dy = coords[s * 3 + 1] - coords[r * 3 + 1];
                float dz = coords[s * 3 + 2] - coords[r * 3 + 2];
                dist = sqrtf(fmaf(dx, dx, fmaf(dy, dy, dz * dz)));
            }
            ss[t] = s; sr[t] = r; sdist[t] = dist;
        }
        __syncthreads();

        // Stage 1: gather + first-layer epilogue + silu (thread owns d = t)
#pragma unroll 4
        for (int e = 0; e < 32; e++) {
            float z = g_P[(size_t)ss[e] * DD + t] + g_Q[(size_t)sr[e] * DD + t]
                    + sdist[e] * wd;
            Xs[t * 33 + e] = fast_silu(z);
        }
        __syncthreads();

        // GEMM: 128 outs x 32 edges, K = 128
        float acc[8][4] = {};
#pragma unroll 8
        for (int k = 0; k < DD; k++) {
            float xv[4];
#pragma unroll
            for (int j = 0; j < 4; j++) xv[j] = Xs[k * 33 + ng * 4 + j];
#pragma unroll
            for (int i = 0; i < 8; i++) {
                float wv = Ws[(dg * 8 + i) * 129 + k];
#pragma unroll
                for (int j = 0; j < 4; j++) acc[i][j] = fmaf(wv, xv[j], acc[i][j]);
            }
        }

        // Epilogue: silu + scatter-add (thread owns 8 contiguous d per edge)
#pragma unroll
        for (int j = 0; j < 4; j++) {
            int e = e0 + ng * 4 + j;
            if (e >= E) continue;
            float* dst = g_agg + (size_t)sr[ng * 4 + j] * DD + dg * 8;
#pragma unroll
            for (int i = 0; i < 8; i++)
                atomicAdd(dst + i, fast_silu(acc[i][j] + b2r[i]));
        }
    }
}

// ---------------------------------------------------------------------------
// Kernel 3: t = silu(U1 @ [h ; agg] + c1)   (K = 256)
// ---------------------------------------------------------------------------
__global__ __launch_bounds__(128) void k_u1(const float* __restrict__ h,
                                            const float* __restrict__ U1,
                                            const float* __restrict__ c1, int N) {
    extern __shared__ float sm[];
    float* Ws = sm;             // [128][257]
    float* Xs = sm + 128 * 257; // [256][33]
    const int t = threadIdx.x;

    for (int idx = t; idx < DD * 256; idx += 128) {
        int d = idx >> 8, k = idx & 255;
        Ws[d * 257 + k] = U1[idx];
    }
    const int l = t & 31, w = t >> 5;
    const int n0 = blockIdx.x * 32;
    for (int r = w; r < 32; r += 4) {
        int node = n0 + r;
        for (int k = l; k < 256; k += 32) {
            float v = 0.f;
            if (node < N)
                v = (k < DD) ? h[(size_t)node * DD + k]
                             : g_agg[(size_t)node * DD + (k - DD)];
            Xs[k * 33 + r] = v;
        }
    }
    __syncthreads();

    const int dg = t >> 3, ng = t & 7; // dg: 0..15
    float acc[8][4] = {};
#pragma unroll 8
    for (int k = 0; k < 256; k++) {
        float xv[4];
#pragma unroll
        for (int j = 0; j < 4; j++) xv[j] = Xs[k * 33 + ng * 4 + j];
#pragma unroll
        for (int i = 0; i < 8; i++) {
            float wv = Ws[(dg * 8 + i) * 257 + k];
#pragma unroll
            for (int j = 0; j < 4; j++) acc[i][j] = fmaf(wv, xv[j], acc[i][j]);
        }
    }
#pragma unroll
    for (int j = 0; j < 4; j++) {
        int node = n0 + ng * 4 + j;
        if (node >= N) continue;
#pragma unroll
        for (int i = 0; i < 8; i++) {
            int d = dg * 8 + i;
            g_t[(size_t)node * DD + d] = fast_silu(acc[i][j] + c1[d]);
        }
    }
}

// ---------------------------------------------------------------------------
// Kernel 4: out = h + U2 @ t + c2   (K = 128)
// ---------------------------------------------------------------------------
__global__ __launch_bounds__(128) void k_u2(const float* __restrict__ h,
                                            const float* __restrict__ U2,
                                            const float* __restrict__ c2,
                                            float* __restrict__ out, int N) {
    extern __shared__ float sm[];
    float* Ws = sm;             // [128][129]
    float* Xs = sm + 128 * 129; // [128][33]
    const int t = threadIdx.x;

    for (int idx = t; idx < DD * DD; idx += 128) {
        int d = idx >> 7, k = idx & 127;
        Ws[d * 129 + k] = U2[idx];
    }
    const int l = t & 31, w = t >> 5;
    const int n0 = blockIdx.x * 32;
    for (int r = w; r < 32; r += 4) {
        int node = n0 + r;
        for (int k = l; k < DD; k += 32)
            Xs[k * 33 + r] = (node < N) ? g_t[(size_t)node * DD + k] : 0.f;
    }
    __syncthreads();

    const int dg = t >> 3, ng = t & 7;
    float acc[8][4] = {};
#pragma unroll 8
    for (int k = 0; k < DD; k++) {
        float xv[4];
#pragma unroll
        for (int j = 0; j < 4; j++) xv[j] = Xs[k * 33 + ng * 4 + j];
#pragma unroll
        for (int i = 0; i < 8; i++) {
            float wv = Ws[(dg * 8 + i) * 129 + k];
#pragma unroll
            for (int j = 0; j < 4; j++) acc[i][j] = fmaf(wv, xv[j], acc[i][j]);
        }
    }
#pragma unroll
    for (int j = 0; j < 4; j++) {
        int node = n0 + ng * 4 + j;
        if (node >= N) continue;
#pragma unroll
        for (int i = 0; i < 8; i++) {
            int d = dg * 8 + i;
            out[(size_t)node * DD + d] =
                h[(size_t)node * DD + d] + acc[i][j] + c2[d];
        }
    }
}

// ---------------------------------------------------------------------------
extern "C" void kernel_launch(void* const* d_in, const int* in_sizes, int n_in,
                              void* d_out, int out_size) {
    const float* h        = (const float*)d_in[0];
    const float* coords   = (const float*)d_in[1];
    const void*  ei       = d_in[2];
    const float* W1       = (const float*)d_in[3];
    const float* b1       = (const float*)d_in[4];
    const float* W2       = (const float*)d_in[5];
    const float* b2       = (const float*)d_in[6];
    const float* U1       = (const float*)d_in[7];
    const float* c1       = (const float*)d_in[8];
    const float* U2       = (const float*)d_in[9];
    const float* c2       = (const float*)d_in[10];
    float* out = (float*)d_out;

    const int N = in_sizes[0] / DD;
    const int E = in_sizes[2] / 2;

    const size_t sm_pq = (256 * 129 + 128 * 33) * sizeof(float);
    const size_t sm_e  = (128 * 129 + 128 * 33 + 32 + 64) * sizeof(float);
    const size_t sm_u1 = (128 * 257 + 256 * 33) * sizeof(float);
    const size_t sm_u2 = (128 * 129 + 128 * 33) * sizeof(float);

    cudaFuncSetAttribute(k_pq,   cudaFuncAttributeMaxDynamicSharedMemorySize, (int)sm_pq);
    cudaFuncSetAttribute(k_edge, cudaFuncAttributeMaxDynamicSharedMemorySize, (int)sm_e);
    cudaFuncSetAttribute(k_u1,   cudaFuncAttributeMaxDynamicSharedMemorySize, (int)sm_u1);
    cudaFuncSetAttribute(k_u2,   cudaFuncAttributeMaxDynamicSharedMemorySize, (int)sm_u2);

    void* aggPtr = nullptr;
    cudaGetSymbolAddress(&aggPtr, g_agg);
    cudaMemsetAsync(aggPtr, 0, (size_t)N * DD * sizeof(float));

    const int nodeTiles = (N + 31) / 32;
    const int edgeTiles = (E + 31) / 32;
    const int edgeGrid = edgeTiles < 1480 ? edgeTiles : 1480;

    k_detect<<<1, 32>>>((const unsigned int*)ei);
    k_conv<<<(2 * E + 255) / 256, 256>>>(ei, 2 * E, N);
    k_pq<<<nodeTiles, 256, sm_pq>>>(h, W1, b1, N);
    k_edge<<<edgeGrid, 128, sm_e>>>(coords, W1, W2, b2, E);
    k_u1<<<nodeTiles, 128, sm_u1>>>(h, U1, c1, N);
    k_u2<<<nodeTiles, 128, sm_u2>>>(h, U2, c2, out, N);
}

// round 3
// speedup vs baseline: 1.4515x; 1.4515x over previous
#include <cuda_runtime.h>
#include <math.h>

#define DD 128
#define MAXN 50000
#define MAXE 800000

__device__ float g_P[MAXN * DD];    // A @ h_n
__device__ float g_Q[MAXN * DD];    // B @ h_n + b1
__device__ float g_agg[MAXN * DD];  // scatter-add target
__device__ float g_t[MAXN * DD];    // silu(U1 @ [h;agg] + c1)
__device__ int   g_eidx[2 * MAXE];  // normalized int32 edge index
__device__ int   g_is64;            // dtype probe result

__device__ __forceinline__ float fast_silu(float x) {
    float hx = 0.5f * x, t;
    asm("tanh.approx.f32 %0, %1;" : "=f"(t) : "f"(hx));
    return fmaf(hx, t, hx);
}

__device__ __forceinline__ void red_add_v4(float* p, float a, float b, float c, float d) {
    asm volatile("red.global.add.v4.f32 [%0], {%1,%2,%3,%4};"
                 :: "l"(p), "f"(a), "f"(b), "f"(c), "f"(d) : "memory");
}

// ---------------------------------------------------------------------------
// Kernel 0a: probe edge_index dtype (int64 values < N have zero high words).
// ---------------------------------------------------------------------------
__global__ void k_detect(const unsigned int* __restrict__ p) {
    if (threadIdx.x == 0) {
        int is64 = 1;
        for (int i = 0; i < 512; i++)
            if (p[2 * i + 1] != 0u) { is64 = 0; break; }
        g_is64 = is64;
    }
}

// Kernel 0b: normalize edge_index -> int32, clamped to [0, N)
__global__ __launch_bounds__(256) void k_conv(const void* __restrict__ ei,
                                              int twoE, int N) {
    int i = blockIdx.x * blockDim.x + threadIdx.x;
    if (i >= twoE) return;
    long long v = g_is64 ? ((const long long*)ei)[i]
                         : (long long)((const int*)ei)[i];
    if (v < 0) v = 0;
    if (v >= N) v = N - 1;
    g_eidx[i] = (int)v;
}

// ---------------------------------------------------------------------------
// Kernel 1: P[n] = A @ h[n], Q[n] = B @ h[n] + b1 (W1 = [A | B | w_d])
// 64-node tiles, 256 threads, 256 outs x 64 nodes, 8x8 per thread.
// ---------------------------------------------------------------------------
__global__ __launch_bounds__(256) void k_pq(const float* __restrict__ h,
                                            const float* __restrict__ W1,
                                            const float* __restrict__ b1, int N) {
    extern __shared__ float sm[];
    float* Ws = sm;             // [256][129]
    float* Xs = sm + 256 * 129; // [128][65]
    const int t = threadIdx.x;

    for (int idx = t; idx < 256 * DD; idx += 256) {
        int d = idx >> 7, k = idx & 127;
        Ws[d * 129 + k] = (d < DD) ? W1[d * 257 + k] : W1[(d - DD) * 257 + DD + k];
    }
    const int l = t & 31, w = t >> 5;
    const int n0 = blockIdx.x * 64;
    for (int r = w; r < 64; r += 8) {
        int node = n0 + r;
        for (int k = l; k < DD; k += 32)
            Xs[k * 65 + r] = (node < N) ? h[(size_t)node * DD + k] : 0.f;
    }
    __syncthreads();

    const int og = t >> 3, ng = t & 7; // 32 out-groups x 8 node-groups
    float acc[8][8] = {};
#pragma unroll 4
    for (int k = 0; k < DD; k++) {
        float xv[8];
#pragma unroll
        for (int j = 0; j < 8; j++) xv[j] = Xs[k * 65 + ng * 8 + j];
#pragma unroll
        for (int i = 0; i < 8; i++) {
            float wv = Ws[(og * 8 + i) * 129 + k];
#pragma unroll
            for (int j = 0; j < 8; j++) acc[i][j] = fmaf(wv, xv[j], acc[i][j]);
        }
    }
#pragma unroll
    for (int j = 0; j < 8; j++) {
        int node = n0 + ng * 8 + j;
        if (node >= N) continue;
        if (og < 16) {
            float* dst = g_P + (size_t)node * DD + og * 8;
#pragma unroll
            for (int i = 0; i < 8; i++) dst[i] = acc[i][j];
        } else {
            int d0 = (og - 16) * 8;
            float* dst = g_Q + (size_t)node * DD + d0;
#pragma unroll
            for (int i = 0; i < 8; i++) dst[i] = acc[i][j] + b1[d0 + i];
        }
    }
}

// ---------------------------------------------------------------------------
// Kernel 2 (edge): 64-edge tiles, 256 threads, 2 CTAs/SM.
//   x = silu(P[s] + Q[r] + dist*w_d); m = silu(W2 @ x + b2); red.v4 into agg.
// ---------------------------------------------------------------------------
__global__ __launch_bounds__(256, 2) void k_edge(const float* __restrict__ coords,
                                                 const float* __restrict__ W1,
                                                 const float* __restrict__ W2,
                                                 const float* __restrict__ b2, int E) {
    extern __shared__ float sm[];
    float* Ws = sm;                  // [128][129]
    float* Xs = sm + 128 * 129;      // [128][65]
    float* sdist = Xs + 128 * 65;    // [64]
    int* ss = (int*)(sdist + 64);    // [64]
    int* sr = ss + 64;               // [64]
    const int t = threadIdx.x;

    for (int idx = t; idx < DD * DD; idx += 256) {
        int d = idx >> 7, k = idx & 127;
        Ws[d * 129 + k] = W2[idx];
    }
    const int dloc = t & 127;            // stage-1 feature owned by this thread
    const int half = t >> 7;             // 0: edges 0-31, 1: edges 32-63
    const float wd = W1[dloc * 257 + 256];
    const int og = t >> 4, eg = t & 15;  // GEMM: 16 out-groups x 16 edge-groups
    float b2r[8];
#pragma unroll
    for (int i = 0; i < 8; i++) b2r[i] = b2[og * 8 + i];

    const int numTiles = (E + 63) >> 6;
    for (int tile = blockIdx.x; tile < numTiles; tile += gridDim.x) {
        const int e0 = tile << 6;
        __syncthreads(); // previous tile's readers done before overwrite
        if (t < 64) {
            int e = e0 + t;
            int s = 0, r = 0;
            float dist = 0.f;
            if (e < E) {
                s = g_eidx[e];
                r = g_eidx[E + e];
                float dx = coords[s * 3 + 0] - coords[r * 3 + 0];
                float dy = coords[s * 3 + 1] - coords[r * 3 + 1];
                float dz = coords[s * 3 + 2] - coords[r * 3 + 2];
                dist = sqrtf(fmaf(dx, dx, fmaf(dy, dy, dz * dz)));
            }
            ss[t] = s; sr[t] = r; sdist[t] = dist;
        }
        __syncthreads();

        // Stage 1: thread owns feature dloc, covers 32 edges of its half
        const int eb = half * 32;
#pragma unroll 8
        for (int e2 = 0; e2 < 32; e2++) {
            int e = eb + e2;
            float z = g_P[(size_t)ss[e] * DD + dloc] + g_Q[(size_t)sr[e] * DD + dloc]
                    + sdist[e] * wd;
            Xs[dloc * 65 + e] = fast_silu(z);
        }
        __syncthreads();

        // GEMM: 128 outs x 64 edges, K=128; 8 outs x 4 edges per thread
        float acc[8][4] = {};
#pragma unroll 8
        for (int k = 0; k < DD; k++) {
            float xv[4];
#pragma unroll
            for (int j = 0; j < 4; j++) xv[j] = Xs[k * 65 + eg * 4 + j];
#pragma unroll
            for (int i = 0; i < 8; i++) {
                float wv = Ws[(og * 8 + i) * 129 + k];
#pragma unroll
                for (int j = 0; j < 4; j++) acc[i][j] = fmaf(wv, xv[j], acc[i][j]);
            }
        }

        // Epilogue: silu + vector scatter-add (2x red.v4 per edge)
#pragma unroll
        for (int j = 0; j < 4; j++) {
            int el = eg * 4 + j;
            if (e0 + el >= E) continue;
            float* dst = g_agg + (size_t)sr[el] * DD + og * 8;
            float v[8];
#pragma unroll
            for (int i = 0; i < 8; i++) v[i] = fast_silu(acc[i][j] + b2r[i]);
            red_add_v4(dst,     v[0], v[1], v[2], v[3]);
            red_add_v4(dst + 4, v[4], v[5], v[6], v[7]);
        }
    }
}

// ---------------------------------------------------------------------------
// Kernel 3: t = silu(U1 @ [h ; agg] + c1)   (K = 256)
// 64-node tiles, 256 threads, 128 outs x 64 nodes, 8x4 per thread.
// ---------------------------------------------------------------------------
__global__ __launch_bounds__(256) void k_u1(const float* __restrict__ h,
                                            const float* __restrict__ U1,
                                            const float* __restrict__ c1, int N) {
    extern __shared__ float sm[];
    float* Ws = sm;             // [128][257]
    float* Xs = sm + 128 * 257; // [256][65]
    const int t = threadIdx.x;

    for (int idx = t; idx < DD * 256; idx += 256) {
        int d = idx >> 8, k = idx & 255;
        Ws[d * 257 + k] = U1[idx];
    }
    const int l = t & 31, w = t >> 5;
    const int n0 = blockIdx.x * 64;
    for (int r = w; r < 64; r += 8) {
        int node = n0 + r;
        for (int k = l; k < 256; k += 32) {
            float v = 0.f;
            if (node < N)
                v = (k < DD) ? h[(size_t)node * DD + k]
                             : g_agg[(size_t)node * DD + (k - DD)];
            Xs[k * 65 + r] = v;
        }
    }
    __syncthreads();

    const int og = t >> 4, ng = t & 15; // 16 out-groups x 16 node-groups
    float acc[8][4] = {};
#pragma unroll 8
    for (int k = 0; k < 256; k++) {
        float xv[4];
#pragma unroll
        for (int j = 0; j < 4; j++) xv[j] = Xs[k * 65 + ng * 4 + j];
#pragma unroll
        for (int i = 0; i < 8; i++) {
            float wv = Ws[(og * 8 + i) * 257 + k];
#pragma unroll
            for (int j = 0; j < 4; j++) acc[i][j] = fmaf(wv, xv[j], acc[i][j]);
        }
    }
#pragma unroll
    for (int j = 0; j < 4; j++) {
        int node = n0 + ng * 4 + j;
        if (node >= N) continue;
        float* dst = g_t + (size_t)node * DD + og * 8;
#pragma unroll
        for (int i = 0; i < 8; i++)
            dst[i] = fast_silu(acc[i][j] + c1[og * 8 + i]);
    }
}

// ---------------------------------------------------------------------------
// Kernel 4: out = h + U2 @ t + c2   (K = 128)
// 64-node tiles, 256 threads, 8x4 per thread.
// ---------------------------------------------------------------------------
__global__ __launch_bounds__(256) void k_u2(const float* __restrict__ h,
                                            const float* __restrict__ U2,
                                            const float* __restrict__ c2,
                                            float* __restrict__ out, int N) {
    extern __shared__ float sm[];
    float* Ws = sm;             // [128][129]
    float* Xs = sm + 128 * 129; // [128][65]
    const int t = threadIdx.x;

    for (int idx = t; idx < DD * DD; idx += 256) {
        int d = idx >> 7, k = idx & 127;
        Ws[d * 129 + k] = U2[idx];
    }
    const int l = t & 31, w = t >> 5;
    const int n0 = blockIdx.x * 64;
    for (int r = w; r < 64; r += 8) {
        int node = n0 + r;
        for (int k = l; k < DD; k += 32)
            Xs[k * 65 + r] = (node < N) ? g_t[(size_t)node * DD + k] : 0.f;
    }
    __syncthreads();

    const int og = t >> 4, ng = t & 15;
    float acc[8][4] = {};
#pragma unroll 8
    for (int k = 0; k < DD; k++) {
        float xv[4];
#pragma unroll
        for (int j = 0; j < 4; j++) xv[j] = Xs[k * 65 + ng * 4 + j];
#pragma unroll
        for (int i = 0; i < 8; i++) {
            float wv = Ws[(og * 8 + i) * 129 + k];
#pragma unroll
            for (int j = 0; j < 4; j++) acc[i][j] = fmaf(wv, xv[j], acc[i][j]);
        }
    }
#pragma unroll
    for (int j = 0; j < 4; j++) {
        int node = n0 + ng * 4 + j;
        if (node >= N) continue;
        const float* hs = h + (size_t)node * DD + og * 8;
        float* dst = out + (size_t)node * DD + og * 8;
#pragma unroll
        for (int i = 0; i < 8; i++)
            dst[i] = hs[i] + acc[i][j] + c2[og * 8 + i];
    }
}

// ---------------------------------------------------------------------------
extern "C" void kernel_launch(void* const* d_in, const int* in_sizes, int n_in,
                              void* d_out, int out_size) {
    const float* h        = (const float*)d_in[0];
    const float* coords   = (const float*)d_in[1];
    const void*  ei       = d_in[2];
    const float* W1       = (const float*)d_in[3];
    const float* b1       = (const float*)d_in[4];
    const float* W2       = (const float*)d_in[5];
    const float* b2       = (const float*)d_in[6];
    const float* U1       = (const float*)d_in[7];
    const float* c1       = (const float*)d_in[8];
    const float* U2       = (const float*)d_in[9];
    const float* c2       = (const float*)d_in[10];
    float* out = (float*)d_out;

    const int N = in_sizes[0] / DD;
    const int E = in_sizes[2] / 2;

    const size_t sm_pq = (256 * 129 + 128 * 65) * sizeof(float);
    const size_t sm_e  = (128 * 129 + 128 * 65 + 64 + 128) * sizeof(float);
    const size_t sm_u1 = (128 * 257 + 256 * 65) * sizeof(float);
    const size_t sm_u2 = (128 * 129 + 128 * 65) * sizeof(float);

    cudaFuncSetAttribute(k_pq,   cudaFuncAttributeMaxDynamicSharedMemorySize, (int)sm_pq);
    cudaFuncSetAttribute(k_edge, cudaFuncAttributeMaxDynamicSharedMemorySize, (int)sm_e);
    cudaFuncSetAttribute(k_u1,   cudaFuncAttributeMaxDynamicSharedMemorySize, (int)sm_u1);
    cudaFuncSetAttribute(k_u2,   cudaFuncAttributeMaxDynamicSharedMemorySize, (int)sm_u2);

    void* aggPtr = nullptr;
    cudaGetSymbolAddress(&aggPtr, g_agg);
    cudaMemsetAsync(aggPtr, 0, (size_t)N * DD * sizeof(float));

    const int nodeTiles = (N + 63) / 64;
    const int edgeTiles = (E + 63) / 64;
    const int edgeGrid = edgeTiles < 296 ? edgeTiles : 296; // 2 CTAs/SM persistent

    k_detect<<<1, 32>>>((const unsigned int*)ei);
    k_conv<<<(2 * E + 255) / 256, 256>>>(ei, 2 * E, N);
    k_pq<<<nodeTiles, 256, sm_pq>>>(h, W1, b1, N);
    k_edge<<<edgeGrid, 256, sm_e>>>(coords, W1, W2, b2, E);
    k_u1<<<nodeTiles, 256, sm_u1>>>(h, U1, c1, N);
    k_u2<<<nodeTiles, 256, sm_u2>>>(h, U2, c2, out, N);
}

// round 5
// speedup vs baseline: 1.5330x; 1.0562x over previous
#include <cuda_runtime.h>
#include <math.h>

#define DD 128
#define MAXN 50000
#define MAXE 800000

__device__ float g_P[MAXN * DD];    // A @ h_n
__device__ float g_Q[MAXN * DD];    // B @ h_n + b1
__device__ float g_agg[MAXN * DD];  // scatter-add target
__device__ float g_t[MAXN * DD];    // silu(U1 @ [h;agg] + c1)
__device__ int   g_eidx[2 * MAXE];  // normalized int32 edge index
__device__ int   g_is64;            // dtype probe result

__device__ __forceinline__ float fast_silu(float x) {
    float hx = 0.5f * x, t;
    asm("tanh.approx.f32 %0, %1;" : "=f"(t) : "f"(hx));
    return fmaf(hx, t, hx);
}

__device__ __forceinline__ void red_add_v4(float* p, float a, float b, float c, float d) {
    asm volatile("red.global.add.v4.f32 [%0], {%1,%2,%3,%4};"
                 :: "l"(p), "f"(a), "f"(b), "f"(c), "f"(d) : "memory");
}

typedef unsigned long long ull;
__device__ __forceinline__ ull pack2(float x, float y) {
    ull r; asm("mov.b64 %0, {%1, %2};" : "=l"(r) : "f"(x), "f"(y)); return r;
}
__device__ __forceinline__ void unpack2(ull v, float& a, float& b) {
    asm("mov.b64 {%0, %1}, %2;" : "=f"(a), "=f"(b) : "l"(v));
}
// d = a * b + d  (packed 2x fp32 — FFMA2, ptxas never auto-fuses this)
__device__ __forceinline__ void fma2(ull& d, ull a, ull b) {
    asm("fma.rn.f32x2 %0, %1, %2, %0;" : "+l"(d) : "l"(a), "l"(b));
}

// ---------------------------------------------------------------------------
// Kernel 0a/0b: edge_index dtype probe + normalize to int32
// ---------------------------------------------------------------------------
__global__ void k_detect(const unsigned int* __restrict__ p) {
    if (threadIdx.x == 0) {
        int is64 = 1;
        for (int i = 0; i < 512; i++)
            if (p[2 * i + 1] != 0u) { is64 = 0; break; }
        g_is64 = is64;
    }
}

__global__ __launch_bounds__(256) void k_conv(const void* __restrict__ ei,
                                              int twoE, int N) {
    int i = blockIdx.x * blockDim.x + threadIdx.x;
    if (i >= twoE) return;
    long long v = g_is64 ? ((const long long*)ei)[i]
                         : (long long)((const int*)ei)[i];
    if (v < 0) v = 0;
    if (v >= N) v = N - 1;
    g_eidx[i] = (int)v;
}

// ---------------------------------------------------------------------------
// Kernel 1: P[n] = A @ h[n], Q[n] = B @ h[n] + b1 (W1 = [A | B | w_d])
// Smem holds W transposed [k][256] so LDS.128 yields (d,d+1) f32x2 pairs.
// 64-node tiles, 256 threads; thread: 8 outs (4 pairs) x 8 nodes (strided).
// ---------------------------------------------------------------------------
__global__ __launch_bounds__(256) void k_pq(const float* __restrict__ h,
                                            const float* __restrict__ W1,
                                            const float* __restrict__ b1, int N) {
    extern __shared__ float sm[];
    float* Wt = sm;             // [128][260]  Wt[k][d], d in 0..255
    float* Xs = sm + 128 * 260; // [128][65]
    const int t = threadIdx.x;

    for (int idx = t; idx < 256 * DD; idx += 256) {
        int d = idx >> 7, k = idx & 127;
        float v = (d < DD) ? W1[d * 257 + k] : W1[(d - DD) * 257 + DD + k];
        Wt[k * 260 + d] = v;
    }
    const int l = t & 31, w = t >> 5;
    const int n0 = blockIdx.x * 64;
    for (int r = w; r < 64; r += 8) {
        int node = n0 + r;
        for (int k = l; k < DD; k += 32)
            Xs[k * 65 + r] = (node < N) ? h[(size_t)node * DD + k] : 0.f;
    }
    __syncthreads();

    const int og = t >> 3, ng = t & 7; // 32 out-groups(8 outs) x 8 node-lanes
    ull acc[4][8] = {};
#pragma unroll 4
    for (int k = 0; k < DD; k++) {
        const float* wr = Wt + k * 260 + og * 8;
        ulonglong2 wa = *(const ulonglong2*)wr;
        ulonglong2 wb = *(const ulonglong2*)(wr + 4);
        ull wv[4] = {wa.x, wa.y, wb.x, wb.y};
#pragma unroll
        for (int j = 0; j < 8; j++) {
            float x = Xs[k * 65 + ng + 8 * j];
            ull xp = pack2(x, x);
#pragma unroll
            for (int p = 0; p < 4; p++) fma2(acc[p][j], wv[p], xp);
        }
    }
#pragma unroll
    for (int j = 0; j < 8; j++) {
        int node = n0 + ng + 8 * j;
        if (node >= N) continue;
        float v[8];
#pragma unroll
        for (int p = 0; p < 4; p++) unpack2(acc[p][j], v[2 * p], v[2 * p + 1]);
        if (og < 16) {
            float4* dst = (float4*)(g_P + (size_t)node * DD + og * 8);
            dst[0] = make_float4(v[0], v[1], v[2], v[3]);
            dst[1] = make_float4(v[4], v[5], v[6], v[7]);
        } else {
            int d0 = (og - 16) * 8;
            float4* dst = (float4*)(g_Q + (size_t)node * DD + d0);
            dst[0] = make_float4(v[0] + b1[d0], v[1] + b1[d0 + 1], v[2] + b1[d0 + 2], v[3] + b1[d0 + 3]);
            dst[1] = make_float4(v[4] + b1[d0 + 4], v[5] + b1[d0 + 5], v[6] + b1[d0 + 6], v[7] + b1[d0 + 7]);
        }
    }
}

// ---------------------------------------------------------------------------
// Kernel 2 (edge): 64-edge tiles, 256 threads, 2 CTAs/SM.
// W2 transposed in smem [k][128]; FFMA2 GEMM; red.v4 scatter.
// Thread: 8 outs (4 d-pairs) x 4 edges (eg + 16j, conflict-free x-loads).
// ---------------------------------------------------------------------------
__global__ __launch_bounds__(256, 2) void k_edge(const float* __restrict__ coords,
                                                 const float* __restrict__ W1,
                                                 const float* __restrict__ W2,
                                                 const float* __restrict__ b2, int E) {
    extern __shared__ float sm[];
    float* Wt = sm;                  // [128][132]  Wt[k][d]
    float* Xs = sm + 128 * 132;      // [128][65]
    float* sdist = Xs + 128 * 65;    // [64]
    int* ss = (int*)(sdist + 64);    // [64]
    int* sr = ss + 64;               // [64]
    const int t = threadIdx.x;

    for (int idx = t; idx < DD * DD; idx += 256) {
        int d = idx >> 7, k = idx & 127;
        Wt[k * 132 + d] = W2[idx];
    }
    const int dloc = t & 127;            // stage-1 feature owned by this thread
    const int half = t >> 7;             // 0: edges 0-31, 1: edges 32-63
    const float wd = W1[dloc * 257 + 256];
    const int og = t >> 4, eg = t & 15;  // 16 out-groups x 16 edge-lanes
    float b2r[8];
#pragma unroll
    for (int i = 0; i < 8; i++) b2r[i] = b2[og * 8 + i];

    const int numTiles = (E + 63) >> 6;
    for (int tile = blockIdx.x; tile < numTiles; tile += gridDim.x) {
        const int e0 = tile << 6;
        __syncthreads(); // previous tile's readers done before overwrite
        if (t < 64) {
            int e = e0 + t;
            int s = 0, r = 0;
            float dist = 0.f;
            if (e < E) {
                s = g_eidx[e];
                r = g_eidx[E + e];
                float dx = coords[s * 3 + 0] - coords[r * 3 + 0];
                float dy = coords[s * 3 + 1] - coords[r * 3 + 1];
                float dz = coords[s * 3 + 2] - coords[r * 3 + 2];
                dist = sqrtf(fmaf(dx, dx, fmaf(dy, dy, dz * dz)));
            }
            ss[t] = s; sr[t] = r; sdist[t] = dist;
        }
        __syncthreads();

        // Stage 1: thread owns feature dloc, covers 32 edges of its half
        const int eb = half * 32;
#pragma unroll 8
        for (int e2 = 0; e2 < 32; e2++) {
            int e = eb + e2;
            float z = g_P[(size_t)ss[e] * DD + dloc] + g_Q[(size_t)sr[e] * DD + dloc]
                    + sdist[e] * wd;
            Xs[dloc * 65 + e] = fast_silu(z);
        }
        __syncthreads();

        // GEMM: 128 outs x 64 edges, K=128, FFMA2
        ull acc[4][4] = {};
#pragma unroll 8
        for (int k = 0; k < DD; k++) {
            const float* wr = Wt + k * 132 + og * 8;
            ulonglong2 wa = *(const ulonglong2*)wr;
            ulonglong2 wb = *(const ulonglong2*)(wr + 4);
            ull wv[4] = {wa.x, wa.y, wb.x, wb.y};
#pragma unroll
            for (int j = 0; j < 4; j++) {
                float x = Xs[k * 65 + eg + 16 * j];
                ull xp = pack2(x, x);
#pragma unroll
                for (int p = 0; p < 4; p++) fma2(acc[p][j], wv[p], xp);
            }
        }

        // Epilogue: silu + vector scatter-add
#pragma unroll
        for (int j = 0; j < 4; j++) {
            int el = eg + 16 * j;
            if (e0 + el >= E) continue;
            float v[8];
#pragma unroll
            for (int p = 0; p < 4; p++) unpack2(acc[p][j], v[2 * p], v[2 * p + 1]);
            float* dst = g_agg + (size_t)sr[el] * DD + og * 8;
#pragma unroll
            for (int i = 0; i < 8; i++) v[i] = fast_silu(v[i] + b2r[i]);
            red_add_v4(dst,     v[0], v[1], v[2], v[3]);
            red_add_v4(dst + 4, v[4], v[5], v[6], v[7]);
        }
    }
}

// ---------------------------------------------------------------------------
// Kernel 3: t = silu(U1 @ [h ; agg] + c1)   (K = 256)
// U1 transposed in smem [k=256][128]; thread: 8 outs (4 pairs) x 4 nodes.
// ---------------------------------------------------------------------------
__global__ __launch_bounds__(256) void k_u1(const float* __restrict__ h,
                                            const float* __restrict__ U1,
                                            const float* __restrict__ c1, int N) {
    extern __shared__ float sm[];
    float* Wt = sm;             // [256][132]
    float* Xs = sm + 256 * 132; // [256][65]
    const int t = threadIdx.x;

    for (int idx = t; idx < DD * 256; idx += 256) {
        int d = idx >> 8, k = idx & 255;
        Wt[k * 132 + d] = U1[idx];
    }
    const int l = t & 31, w = t >> 5;
    const int n0 = blockIdx.x * 64;
    for (int r = w; r < 64; r += 8) {
        int node = n0 + r;
        for (int k = l; k < 256; k += 32) {
            float v = 0.f;
            if (node < N)
                v = (k < DD) ? h[(size_t)node * DD + k]
                             : g_agg[(size_t)node * DD + (k - DD)];
            Xs[k * 65 + r] = v;
        }
    }
    __syncthreads();

    const int og = t >> 4, ng = t & 15;
    ull acc[4][4] = {};
#pragma unroll 8
    for (int k = 0; k < 256; k++) {
        const float* wr = Wt + k * 132 + og * 8;
        ulonglong2 wa = *(const ulonglong2*)wr;
        ulonglong2 wb = *(const ulonglong2*)(wr + 4);
        ull wv[4] = {wa.x, wa.y, wb.x, wb.y};
#pragma unroll
        for (int j = 0; j < 4; j++) {
            float x = Xs[k * 65 + ng + 16 * j];
            ull xp = pack2(x, x);
#pragma unroll
            for (int p = 0; p < 4; p++) fma2(acc[p][j], wv[p], xp);
        }
    }
#pragma unroll
    for (int j = 0; j < 4; j++) {
        int node = n0 + ng + 16 * j;
        if (node >= N) continue;
        float v[8];
#pragma unroll
        for (int p = 0; p < 4; p++) unpack2(acc[p][j], v[2 * p], v[2 * p + 1]);
        float* dst = g_t + (size_t)node * DD + og * 8;
#pragma unroll
        for (int i = 0; i < 8; i++)
            dst[i] = fast_silu(v[i] + c1[og * 8 + i]);
    }
}

// ---------------------------------------------------------------------------
// Kernel 4: out = h + U2 @ t + c2   (K = 128)
// ---------------------------------------------------------------------------
__global__ __launch_bounds__(256) void k_u2(const float* __restrict__ h,
                                            const float* __restrict__ U2,
                                            const float* __restrict__ c2,
                                            float* __restrict__ out, int N) {
    extern __shared__ float sm[];
    float* Wt = sm;             // [128][132]
    float* Xs = sm + 128 * 132; // [128][65]
    const int t = threadIdx.x;

    for (int idx = t; idx < DD * DD; idx += 256) {
        int d = idx >> 7, k = idx & 127;
        Wt[k * 132 + d] = U2[idx];
    }
    const int l = t & 31, w = t >> 5;
    const int n0 = blockIdx.x * 64;
    for (int r = w; r < 64; r += 8) {
        int node = n0 + r;
        for (int k = l; k < DD; k += 32)
            Xs[k * 65 + r] = (node < N) ? g_t[(size_t)node * DD + k] : 0.f;
    }
    __syncthreads();

    const int og = t >> 4, ng = t & 15;
    ull acc[4][4] = {};
#pragma unroll 8
    for (int k = 0; k < DD; k++) {
        const float* wr = Wt + k * 132 + og * 8;
        ulonglong2 wa = *(const ulonglong2*)wr;
        ulonglong2 wb = *(const ulonglong2*)(wr + 4);
        ull wv[4] = {wa.x, wa.y, wb.x, wb.y};
#pragma unroll
        for (int j = 0; j < 4; j++) {
            float x = Xs[k * 65 + ng + 16 * j];
            ull xp = pack2(x, x);
#pragma unroll
            for (int p = 0; p < 4; p++) fma2(acc[p][j], wv[p], xp);
        }
    }
#pragma unroll
    for (int j = 0; j < 4; j++) {
        int node = n0 + ng + 16 * j;
        if (node >= N) continue;
        float v[8];
#pragma unroll
        for (int p = 0; p < 4; p++) unpack2(acc[p][j], v[2 * p], v[2 * p + 1]);
        const float* hs = h + (size_t)node * DD + og * 8;
        float* dst = out + (size_t)node * DD + og * 8;
#pragma unroll
        for (int i = 0; i < 8; i++)
            dst[i] = hs[i] + v[i] + c2[og * 8 + i];
    }
}

// ---------------------------------------------------------------------------
extern "C" void kernel_launch(void* const* d_in, const int* in_sizes, int n_in,
                              void* d_out, int out_size) {
    const float* h        = (const float*)d_in[0];
    const float* coords   = (const float*)d_in[1];
    const void*  ei       = d_in[2];
    const float* W1       = (const float*)d_in[3];
    const float* b1       = (const float*)d_in[4];
    const float* W2       = (const float*)d_in[5];
    const float* b2       = (const float*)d_in[6];
    const float* U1       = (const float*)d_in[7];
    const float* c1       = (const float*)d_in[8];
    const float* U2       = (const float*)d_in[9];
    const float* c2       = (const float*)d_in[10];
    float* out = (float*)d_out;

    const int N = in_sizes[0] / DD;
    const int E = in_sizes[2] / 2;

    const size_t sm_pq = (128 * 260 + 128 * 65) * sizeof(float);
    const size_t sm_e  = (128 * 132 + 128 * 65 + 64 + 128) * sizeof(float);
    const size_t sm_u1 = (256 * 132 + 256 * 65) * sizeof(float);
    const size_t sm_u2 = (128 * 132 + 128 * 65) * sizeof(float);

    cudaFuncSetAttribute(k_pq,   cudaFuncAttributeMaxDynamicSharedMemorySize, (int)sm_pq);
    cudaFuncSetAttribute(k_edge, cudaFuncAttributeMaxDynamicSharedMemorySize, (int)sm_e);
    cudaFuncSetAttribute(k_u1,   cudaFuncAttributeMaxDynamicSharedMemorySize, (int)sm_u1);
    cudaFuncSetAttribute(k_u2,   cudaFuncAttributeMaxDynamicSharedMemorySize, (int)sm_u2);

    void* aggPtr = nullptr;
    cudaGetSymbolAddress(&aggPtr, g_agg);
    cudaMemsetAsync(aggPtr, 0, (size_t)N * DD * sizeof(float));

    const int nodeTiles = (N + 63) / 64;
    const int edgeTiles = (E + 63) / 64;
    const int edgeGrid = edgeTiles < 296 ? edgeTiles : 296; // 2 CTAs/SM persistent

    k_detect<<<1, 32>>>((const unsigned int*)ei);
    k_conv<<<(2 * E + 255) / 256, 256>>>(ei, 2 * E, N);
    k_pq<<<nodeTiles, 256, sm_pq>>>(h, W1, b1, N);
    k_edge<<<edgeGrid, 256, sm_e>>>(coords, W1, W2, b2, E);
    k_u1<<<nodeTiles, 256, sm_u1>>>(h, U1, c1, N);
    k_u2<<<nodeTiles, 256, sm_u2>>>(h, U2, c2, out, N);
}

// round 6
// speedup vs baseline: 2.1520x; 1.4037x over previous
#include <cuda_runtime.h>
#include <math.h>

#define DD 128
#define MAXN 50000
#define MAXE 800000

__device__ float g_P[MAXN * DD];    // A @ h_n
__device__ float g_Q[MAXN * DD];    // B @ h_n + b1
__device__ float g_agg[MAXN * DD];  // scatter-add target
__device__ float g_t[MAXN * DD];    // silu(U1 @ [h;agg] + c1)
__device__ int   g_eidx[2 * MAXE];  // normalized int32 edge index
__device__ int   g_is64;            // dtype probe result

__device__ __forceinline__ float fast_silu(float x) {
    float hx = 0.5f * x, t;
    asm("tanh.approx.f32 %0, %1;" : "=f"(t) : "f"(hx));
    return fmaf(hx, t, hx);
}

__device__ __forceinline__ void red_add_v2(float* p, float a, float b) {
    asm volatile("red.global.add.v2.f32 [%0], {%1,%2};"
                 :: "l"(p), "f"(a), "f"(b) : "memory");
}

typedef unsigned long long ull;
__device__ __forceinline__ void unpack2(ull v, float& a, float& b) {
    asm("mov.b64 {%0, %1}, %2;" : "=f"(a), "=f"(b) : "l"(v));
}
__device__ __forceinline__ ull pack2(float x, float y) {
    ull r; asm("mov.b64 %0, {%1, %2};" : "=l"(r) : "f"(x), "f"(y)); return r;
}
__device__ __forceinline__ void fma2(ull& d, ull a, ull b) {
    asm("fma.rn.f32x2 %0, %1, %2, %0;" : "+l"(d) : "l"(a), "l"(b));
}

__device__ __forceinline__ float tf32f(float x) {
    unsigned u; asm("cvt.rna.tf32.f32 %0, %1;" : "=r"(u) : "f"(x));
    return __uint_as_float(u);
}

// m16n8k8 tf32 mma: A row-major (16x8), B col-major (8x8), fp32 accum
__device__ __forceinline__ void mma_tf32(float* c, float a0, float a1, float a2,
                                         float a3, float b0, float b1) {
    asm volatile(
        "mma.sync.aligned.m16n8k8.row.col.f32.tf32.tf32.f32 "
        "{%0,%1,%2,%3}, {%4,%5,%6,%7}, {%8,%9}, {%0,%1,%2,%3};"
        : "+f"(c[0]), "+f"(c[1]), "+f"(c[2]), "+f"(c[3])
        : "r"(__float_as_uint(a0)), "r"(__float_as_uint(a1)),
          "r"(__float_as_uint(a2)), "r"(__float_as_uint(a3)),
          "r"(__float_as_uint(b0)), "r"(__float_as_uint(b1)));
}

// ---------------------------------------------------------------------------
// Kernel 0a/0b: edge_index dtype probe + normalize to int32
// ---------------------------------------------------------------------------
__global__ void k_detect(const unsigned int* __restrict__ p) {
    if (threadIdx.x == 0) {
        int is64 = 1;
        for (int i = 0; i < 512; i++)
            if (p[2 * i + 1] != 0u) { is64 = 0; break; }
        g_is64 = is64;
    }
}

__global__ __launch_bounds__(256) void k_conv(const void* __restrict__ ei,
                                              int twoE, int N) {
    int i = blockIdx.x * blockDim.x + threadIdx.x;
    if (i >= twoE) return;
    long long v = g_is64 ? ((const long long*)ei)[i]
                         : (long long)((const int*)ei)[i];
    if (v < 0) v = 0;
    if (v >= N) v = N - 1;
    g_eidx[i] = (int)v;
}

// ---------------------------------------------------------------------------
// Kernel 1: blockIdx.y = 0 -> P[n] = A @ h[n];  1 -> Q[n] = B @ h[n] + b1
// Wt half [128k][132d] (67.6KB) + Xs [128][65] -> 2 CTAs/SM. FFMA2 GEMM.
// ---------------------------------------------------------------------------
__global__ __launch_bounds__(256) void k_pq(const float* __restrict__ h,
                                            const float* __restrict__ W1,
                                            const float* __restrict__ b1, int N) {
    extern __shared__ float sm[];
    float* Wt = sm;             // [128 k][132 d]
    float* Xs = sm + 128 * 132; // [128 k][65]
    const int t = threadIdx.x;
    const int half = blockIdx.y;

    for (int idx = t; idx < DD * DD; idx += 256) {
        int d = idx >> 7, k = idx & 127;
        float v = half ? W1[d * 257 + DD + k] : W1[d * 257 + k];
        Wt[k * 132 + d] = v;
    }
    const int l = t & 31, w = t >> 5;
    const int n0 = blockIdx.x * 64;
    for (int r = w; r < 64; r += 8) {
        int node = n0 + r;
        for (int k = l; k < DD; k += 32)
            Xs[k * 65 + r] = (node < N) ? h[(size_t)node * DD + k] : 0.f;
    }
    __syncthreads();

    const int og = t >> 4, ng = t & 15;
    ull acc[4][4] = {};
#pragma unroll 8
    for (int k = 0; k < DD; k++) {
        const float* wr = Wt + k * 132 + og * 8;
        ulonglong2 wa = *(const ulonglong2*)wr;
        ulonglong2 wb = *(const ulonglong2*)(wr + 4);
        ull wv[4] = {wa.x, wa.y, wb.x, wb.y};
#pragma unroll
        for (int j = 0; j < 4; j++) {
            float x = Xs[k * 65 + ng + 16 * j];
            ull xp = pack2(x, x);
#pragma unroll
            for (int p = 0; p < 4; p++) fma2(acc[p][j], wv[p], xp);
        }
    }
#pragma unroll
    for (int j = 0; j < 4; j++) {
        int node = n0 + ng + 16 * j;
        if (node >= N) continue;
        float v[8];
#pragma unroll
        for (int p = 0; p < 4; p++) unpack2(acc[p][j], v[2 * p], v[2 * p + 1]);
        int d0 = og * 8;
        if (half == 0) {
            float4* dst = (float4*)(g_P + (size_t)node * DD + d0);
            dst[0] = make_float4(v[0], v[1], v[2], v[3]);
            dst[1] = make_float4(v[4], v[5], v[6], v[7]);
        } else {
            float4* dst = (float4*)(g_Q + (size_t)node * DD + d0);
            dst[0] = make_float4(v[0] + b1[d0], v[1] + b1[d0 + 1], v[2] + b1[d0 + 2], v[3] + b1[d0 + 3]);
            dst[1] = make_float4(v[4] + b1[d0 + 4], v[5] + b1[d0 + 5], v[6] + b1[d0 + 6], v[7] + b1[d0 + 7]);
        }
    }
}

// ---------------------------------------------------------------------------
// Kernel 2 (edge): tf32 tensor-core GEMM. 64-edge tiles, 256 threads, 2/SM.
//   stage1: x[e][k] = tf32(silu(P[s]+Q[r]+dist*wd))  (edge-major Xs)
//   mma:    out[64 e][128 d] = Xs @ Ws^T  via m16n8k8 tf32
//   epi:    silu + red.v2 scatter into g_agg
// ---------------------------------------------------------------------------
__global__ __launch_bounds__(256, 2) void k_edge(const float* __restrict__ coords,
                                                 const float* __restrict__ W1,
                                                 const float* __restrict__ W2,
                                                 const float* __restrict__ b2, int E) {
    extern __shared__ float sm[];
    float* Ws = sm;                  // [128 d][132 k]  W2 row-major, tf32
    float* Xs = sm + 128 * 132;      // [64 e][132 k]   tf32
    float* sdist = Xs + 64 * 132;    // [64]
    int* ss = (int*)(sdist + 64);    // [64]
    int* sr = ss + 64;               // [64]
    const int t = threadIdx.x;

    for (int idx = t; idx < DD * DD; idx += 256) {
        int d = idx >> 7, k = idx & 127;
        Ws[d * 132 + k] = tf32f(W2[idx]);
    }
    const int dloc = t & 127, half = t >> 7;
    const float wd = W1[dloc * 257 + 256];
    const int warp = t >> 5, lane = t & 31, g = lane >> 2, tg = lane & 3;
    const int mt = warp >> 1;       // 4 m-tiles of 16 edges
    const int nh = warp & 1;        // d-half: 0 -> d 0..63, 1 -> 64..127
    float b2a[8], b2b[8];
#pragma unroll
    for (int nt = 0; nt < 8; nt++) {
        int d = nh * 64 + nt * 8 + 2 * tg;
        b2a[nt] = b2[d]; b2b[nt] = b2[d + 1];
    }

    const int numTiles = (E + 63) >> 6;
    for (int tile = blockIdx.x; tile < numTiles; tile += gridDim.x) {
        const int e0 = tile << 6;
        __syncthreads();
        if (t < 64) {
            int e = e0 + t;
            int s = 0, r = 0;
            float dist = 0.f;
            if (e < E) {
                s = g_eidx[e];
                r = g_eidx[E + e];
                float dx = coords[s * 3 + 0] - coords[r * 3 + 0];
                float dy = coords[s * 3 + 1] - coords[r * 3 + 1];
                float dz = coords[s * 3 + 2] - coords[r * 3 + 2];
                dist = sqrtf(fmaf(dx, dx, fmaf(dy, dy, dz * dz)));
            }
            ss[t] = s; sr[t] = r; sdist[t] = dist;
        }
        __syncthreads();

        // Stage 1: thread owns feature dloc over 32 edges of its half
        const int eb = half * 32;
#pragma unroll 8
        for (int e2 = 0; e2 < 32; e2++) {
            int e = eb + e2;
            float z = g_P[(size_t)ss[e] * DD + dloc] + g_Q[(size_t)sr[e] * DD + dloc]
                    + sdist[e] * wd;
            Xs[e * 132 + dloc] = tf32f(fast_silu(z));
        }
        __syncthreads();

        // mma: warp computes [16 edges] x [64 d]; K = 128 in 16 ksteps
        float acc[8][4] = {};
#pragma unroll
        for (int ks = 0; ks < 16; ks++) {
            const int k0 = ks * 8;
            const float* xr = Xs + (mt * 16 + g) * 132 + k0 + tg;
            float a0 = xr[0];
            float a2 = xr[4];
            float a1 = xr[8 * 132];
            float a3 = xr[8 * 132 + 4];
#pragma unroll
            for (int nt = 0; nt < 8; nt++) {
                const float* wr = Ws + (nh * 64 + nt * 8 + g) * 132 + k0 + tg;
                mma_tf32(acc[nt], a0, a1, a2, a3, wr[0], wr[4]);
            }
        }

        // Epilogue: silu + red.v2 scatter
        const int er0 = mt * 16 + g;
        const bool ok0 = (e0 + er0) < E;
        const bool ok1 = (e0 + er0 + 8) < E;
        const int r0 = sr[er0], r1 = sr[er0 + 8];
#pragma unroll
        for (int nt = 0; nt < 8; nt++) {
            int d = nh * 64 + nt * 8 + 2 * tg;
            if (ok0) {
                float v0 = fast_silu(acc[nt][0] + b2a[nt]);
                float v1 = fast_silu(acc[nt][1] + b2b[nt]);
                red_add_v2(g_agg + (size_t)r0 * DD + d, v0, v1);
            }
            if (ok1) {
                float v2 = fast_silu(acc[nt][2] + b2a[nt]);
                float v3 = fast_silu(acc[nt][3] + b2b[nt]);
                red_add_v2(g_agg + (size_t)r1 * DD + d, v2, v3);
            }
        }
    }
}

// ---------------------------------------------------------------------------
// Kernel 3: t = silu(U1 @ [h ; agg] + c1), K=256, blockIdx.y = d-half.
// Wt [256k][68dl] + Xs [128][65] two-phase K staging -> 2 CTAs/SM.
// ---------------------------------------------------------------------------
__global__ __launch_bounds__(256) void k_u1(const float* __restrict__ h,
                                            const float* __restrict__ U1,
                                            const float* __restrict__ c1, int N) {
    extern __shared__ float sm[];
    float* Wt = sm;            // [256 k][68 dl]
    float* Xs = sm + 256 * 68; // [128 k][65]
    const int t = threadIdx.x;
    const int half = blockIdx.y;

    for (int idx = t; idx < 64 * 256; idx += 256) {
        int dl = idx >> 8, k = idx & 255;
        Wt[k * 68 + dl] = U1[(size_t)(half * 64 + dl) * 256 + k];
    }
    const int l = t & 31, w = t >> 5;
    const int n0 = blockIdx.x * 64;
    const int og = t >> 5, ng = t & 31;
    ull acc[4][2] = {};

    // Phase 0: k in [0,128) from h
    for (int r = w; r < 64; r += 8) {
        int node = n0 + r;
        for (int k = l; k < DD; k += 32)
            Xs[k * 65 + r] = (node < N) ? h[(size_t)node * DD + k] : 0.f;
    }
    __syncthreads();
#pragma unroll 8
    for (int k = 0; k < DD; k++) {
        const float* wr = Wt + k * 68 + og * 8;
        ulonglong2 wa = *(const ulonglong2*)wr;
        ulonglong2 wb = *(const ulonglong2*)(wr + 4);
        ull wv[4] = {wa.x, wa.y, wb.x, wb.y};
#pragma unroll
        for (int j = 0; j < 2; j++) {
            float x = Xs[k * 65 + ng + 32 * j];
            ull xp = pack2(x, x);
#pragma unroll
            for (int p = 0; p < 4; p++) fma2(acc[p][j], wv[p], xp);
        }
    }
    __syncthreads();

    // Phase 1: k in [128,256) from agg
    for (int r = w; r < 64; r += 8) {
        int node = n0 + r;
        for (int k = l; k < DD; k += 32)
            Xs[k * 65 + r] = (node < N) ? g_agg[(size_t)node * DD + k] : 0.f;
    }
    __syncthreads();
#pragma unroll 8
    for (int k = 0; k < DD; k++) {
        const float* wr = Wt + (DD + k) * 68 + og * 8;
        ulonglong2 wa = *(const ulonglong2*)wr;
        ulonglong2 wb = *(const ulonglong2*)(wr + 4);
        ull wv[4] = {wa.x, wa.y, wb.x, wb.y};
#pragma unroll
        for (int j = 0; j < 2; j++) {
            float x = Xs[k * 65 + ng + 32 * j];
            ull xp = pack2(x, x);
#pragma unroll
            for (int p = 0; p < 4; p++) fma2(acc[p][j], wv[p], xp);
        }
    }

#pragma unroll
    for (int j = 0; j < 2; j++) {
        int node = n0 + ng + 32 * j;
        if (node >= N) continue;
        float v[8];
#pragma unroll
        for (int p = 0; p < 4; p++) unpack2(acc[p][j], v[2 * p], v[2 * p + 1]);
        int d0 = half * 64 + og * 8;
        float* dst = g_t + (size_t)node * DD + d0;
#pragma unroll
        for (int i = 0; i < 8; i++)
            dst[i] = fast_silu(v[i] + c1[d0 + i]);
    }
}

// ---------------------------------------------------------------------------
// Kernel 4: out = h + U2 @ t + c2, K=128, blockIdx.y = d-half. 3 CTAs/SM.
// ---------------------------------------------------------------------------
__global__ __launch_bounds__(256, 3) void k_u2(const float* __restrict__ h,
                                               const float* __restrict__ U2,
                                               const float* __restrict__ c2,
                                               float* __restrict__ out, int N) {
    extern __shared__ float sm[];
    float* Wt = sm;            // [128 k][68 dl]
    float* Xs = sm + 128 * 68; // [128 k][65]
    const int t = threadIdx.x;
    const int half = blockIdx.y;

    for (int idx = t; idx < 64 * DD; idx += 256) {
        int dl = idx >> 7, k = idx & 127;
        Wt[k * 68 + dl] = U2[(size_t)(half * 64 + dl) * DD + k];
    }
    const int l = t & 31, w = t >> 5;
    const int n0 = blockIdx.x * 64;
    for (int r = w; r < 64; r += 8) {
        int node = n0 + r;
        for (int k = l; k < DD; k += 32)
            Xs[k * 65 + r] = (node < N) ? g_t[(size_t)node * DD + k] : 0.f;
    }
    __syncthreads();

    const int og = t >> 5, ng = t & 31;
    ull acc[4][2] = {};
#pragma unroll 8
    for (int k = 0; k < DD; k++) {
        const float* wr = Wt + k * 68 + og * 8;
        ulonglong2 wa = *(const ulonglong2*)wr;
        ulonglong2 wb = *(const ulonglong2*)(wr + 4);
        ull wv[4] = {wa.x, wa.y, wb.x, wb.y};
#pragma unroll
        for (int j = 0; j < 2; j++) {
            float x = Xs[k * 65 + ng + 32 * j];
            ull xp = pack2(x, x);
#pragma unroll
            for (int p = 0; p < 4; p++) fma2(acc[p][j], wv[p], xp);
        }
    }
#pragma unroll
    for (int j = 0; j < 2; j++) {
        int node = n0 + ng + 32 * j;
        if (node >= N) continue;
        float v[8];
#pragma unroll
        for (int p = 0; p < 4; p++) unpack2(acc[p][j], v[2 * p], v[2 * p + 1]);
        int d0 = half * 64 + og * 8;
        const float* hs = h + (size_t)node * DD + d0;
        float* dst = out + (size_t)node * DD + d0;
#pragma unroll
        for (int i = 0; i < 8; i++)
            dst[i] = hs[i] + v[i] + c2[d0 + i];
    }
}

// ---------------------------------------------------------------------------
extern "C" void kernel_launch(void* const* d_in, const int* in_sizes, int n_in,
                              void* d_out, int out_size) {
    const float* h        = (const float*)d_in[0];
    const float* coords   = (const float*)d_in[1];
    const void*  ei       = d_in[2];
    const float* W1       = (const float*)d_in[3];
    const float* b1       = (const float*)d_in[4];
    const float* W2       = (const float*)d_in[5];
    const float* b2       = (const float*)d_in[6];
    const float* U1       = (const float*)d_in[7];
    const float* c1       = (const float*)d_in[8];
    const float* U2       = (const float*)d_in[9];
    const float* c2       = (const float*)d_in[10];
    float* out = (float*)d_out;

    const int N = in_sizes[0] / DD;
    const int E = in_sizes[2] / 2;

    const size_t sm_pq = (128 * 132 + 128 * 65) * sizeof(float);
    const size_t sm_e  = (128 * 132 + 64 * 132 + 64 + 128) * sizeof(float);
    const size_t sm_u1 = (256 * 68 + 128 * 65) * sizeof(float);
    const size_t sm_u2 = (128 * 68 + 128 * 65) * sizeof(float);

    cudaFuncSetAttribute(k_pq,   cudaFuncAttributeMaxDynamicSharedMemorySize, (int)sm_pq);
    cudaFuncSetAttribute(k_edge, cudaFuncAttributeMaxDynamicSharedMemorySize, (int)sm_e);
    cudaFuncSetAttribute(k_u1,   cudaFuncAttributeMaxDynamicSharedMemorySize, (int)sm_u1);
    cudaFuncSetAttribute(k_u2,   cudaFuncAttributeMaxDynamicSharedMemorySize, (int)sm_u2);

    void* aggPtr = nullptr;
    cudaGetSymbolAddress(&aggPtr, g_agg);
    cudaMemsetAsync(aggPtr, 0, (size_t)N * DD * sizeof(float));

    const int nodeTiles = (N + 63) / 64;
    const int edgeTiles = (E + 63) / 64;
    const int edgeGrid = edgeTiles < 296 ? edgeTiles : 296;

    dim3 gPQ(nodeTiles, 2), gU1(nodeTiles, 2), gU2(nodeTiles, 2);

    k_detect<<<1, 32>>>((const unsigned int*)ei);
    k_conv<<<(2 * E + 255) / 256, 256>>>(ei, 2 * E, N);
    k_pq<<<gPQ, 256, sm_pq>>>(h, W1, b1, N);
    k_edge<<<edgeGrid, 256, sm_e>>>(coords, W1, W2, b2, E);
    k_u1<<<gU1, 256, sm_u1>>>(h, U1, c1, N);
    k_u2<<<gU2, 256, sm_u2>>>(h, U2, c2, out, N);
}

// round 7
// speedup vs baseline: 3.1719x; 1.4739x over previous
#include <cuda_runtime.h>
#include <math.h>

#define DD 128
#define MAXN 50000
#define MAXE 800000

__device__ float g_P[MAXN * DD];    // A @ h_n
__device__ float g_Q[MAXN * DD];    // B @ h_n + b1
__device__ float g_agg[MAXN * DD];  // scatter-add target
__device__ float g_t[MAXN * DD];    // silu(U1 @ [h;agg] + c1)
__device__ int   g_eidx[2 * MAXE];  // normalized int32 edge index
__device__ int   g_is64;            // dtype probe result

__device__ __forceinline__ float fast_silu(float x) {
    float hx = 0.5f * x, t;
    asm("tanh.approx.f32 %0, %1;" : "=f"(t) : "f"(hx));
    return fmaf(hx, t, hx);
}

__device__ __forceinline__ void red_add_v2(float* p, float a, float b) {
    asm volatile("red.global.add.v2.f32 [%0], {%1,%2};"
                 :: "l"(p), "f"(a), "f"(b) : "memory");
}

typedef unsigned long long ull;
__device__ __forceinline__ void unpack2(ull v, float& a, float& b) {
    asm("mov.b64 {%0, %1}, %2;" : "=f"(a), "=f"(b) : "l"(v));
}
__device__ __forceinline__ ull pack2(float x, float y) {
    ull r; asm("mov.b64 %0, {%1, %2};" : "=l"(r) : "f"(x), "f"(y)); return r;
}
__device__ __forceinline__ void fma2(ull& d, ull a, ull b) {
    asm("fma.rn.f32x2 %0, %1, %2, %0;" : "+l"(d) : "l"(a), "l"(b));
}

// pack (lo, hi) fp32 -> f16x2
__device__ __forceinline__ unsigned f16x2(float lo, float hi) {
    unsigned r;
    asm("cvt.rn.f16x2.f32 %0, %1, %2;" : "=r"(r) : "f"(hi), "f"(lo));
    return r;
}

// m16n8k16 f16 mma: A row-major (16x16), B col-major (16x8), fp32 accum
__device__ __forceinline__ void mma_f16(float* c, unsigned a0, unsigned a1,
                                        unsigned a2, unsigned a3,
                                        unsigned b0, unsigned b1) {
    asm volatile(
        "mma.sync.aligned.m16n8k16.row.col.f32.f16.f16.f32 "
        "{%0,%1,%2,%3}, {%4,%5,%6,%7}, {%8,%9}, {%0,%1,%2,%3};"
        : "+f"(c[0]), "+f"(c[1]), "+f"(c[2]), "+f"(c[3])
        : "r"(a0), "r"(a1), "r"(a2), "r"(a3), "r"(b0), "r"(b1));
}

// ---------------------------------------------------------------------------
// Kernel 0a/0b: edge_index dtype probe + normalize to int32
// ---------------------------------------------------------------------------
__global__ void k_detect(const unsigned int* __restrict__ p) {
    if (threadIdx.x == 0) {
        int is64 = 1;
        for (int i = 0; i < 512; i++)
            if (p[2 * i + 1] != 0u) { is64 = 0; break; }
        g_is64 = is64;
    }
}

__global__ __launch_bounds__(256) void k_conv(const void* __restrict__ ei,
                                              int twoE, int N) {
    int i = blockIdx.x * blockDim.x + threadIdx.x;
    if (i >= twoE) return;
    long long v = g_is64 ? ((const long long*)ei)[i]
                         : (long long)((const int*)ei)[i];
    if (v < 0) v = 0;
    if (v >= N) v = N - 1;
    g_eidx[i] = (int)v;
}

// ---------------------------------------------------------------------------
// Kernel 1: blockIdx.y = 0 -> P[n] = A @ h[n];  1 -> Q[n] = B @ h[n] + b1
// ---------------------------------------------------------------------------
__global__ __launch_bounds__(256) void k_pq(const float* __restrict__ h,
                                            const float* __restrict__ W1,
                                            const float* __restrict__ b1, int N) {
    extern __shared__ float sm[];
    float* Wt = sm;             // [128 k][132 d]
    float* Xs = sm + 128 * 132; // [128 k][65]
    const int t = threadIdx.x;
    const int half = blockIdx.y;

    for (int idx = t; idx < DD * DD; idx += 256) {
        int d = idx >> 7, k = idx & 127;
        float v = half ? W1[d * 257 + DD + k] : W1[d * 257 + k];
        Wt[k * 132 + d] = v;
    }
    const int l = t & 31, w = t >> 5;
    const int n0 = blockIdx.x * 64;
    for (int r = w; r < 64; r += 8) {
        int node = n0 + r;
        for (int k = l; k < DD; k += 32)
            Xs[k * 65 + r] = (node < N) ? h[(size_t)node * DD + k] : 0.f;
    }
    __syncthreads();

    const int og = t >> 4, ng = t & 15;
    ull acc[4][4] = {};
#pragma unroll 8
    for (int k = 0; k < DD; k++) {
        const float* wr = Wt + k * 132 + og * 8;
        ulonglong2 wa = *(const ulonglong2*)wr;
        ulonglong2 wb = *(const ulonglong2*)(wr + 4);
        ull wv[4] = {wa.x, wa.y, wb.x, wb.y};
#pragma unroll
        for (int j = 0; j < 4; j++) {
            float x = Xs[k * 65 + ng + 16 * j];
            ull xp = pack2(x, x);
#pragma unroll
            for (int p = 0; p < 4; p++) fma2(acc[p][j], wv[p], xp);
        }
    }
#pragma unroll
    for (int j = 0; j < 4; j++) {
        int node = n0 + ng + 16 * j;
        if (node >= N) continue;
        float v[8];
#pragma unroll
        for (int p = 0; p < 4; p++) unpack2(acc[p][j], v[2 * p], v[2 * p + 1]);
        int d0 = og * 8;
        if (half == 0) {
            float4* dst = (float4*)(g_P + (size_t)node * DD + d0);
            dst[0] = make_float4(v[0], v[1], v[2], v[3]);
            dst[1] = make_float4(v[4], v[5], v[6], v[7]);
        } else {
            float4* dst = (float4*)(g_Q + (size_t)node * DD + d0);
            dst[0] = make_float4(v[0] + b1[d0], v[1] + b1[d0 + 1], v[2] + b1[d0 + 2], v[3] + b1[d0 + 3]);
            dst[1] = make_float4(v[4] + b1[d0 + 4], v[5] + b1[d0 + 5], v[6] + b1[d0 + 6], v[7] + b1[d0 + 7]);
        }
    }
}

// ---------------------------------------------------------------------------
// Kernel 2 (edge): fp16 tensor-core GEMM, 64-edge tiles, 256 thr, 4 CTAs/SM.
// smem (words): Ws2 [0,8704) = W2 half2 [128 d][68]; Xs2 [8704,13056) =
// x half2 [64 e][68]; b2s [13056,13184); sdist/ss/sr after.
//   stage1: thread owns feature pair dp over 16 edges (float2 gather)
//   mma:    m16n8k16.f16, warp = 16 edges x 64 d
//   epi:    silu + red.v2 scatter
// ---------------------------------------------------------------------------
__global__ __launch_bounds__(256, 4) void k_edge(const float* __restrict__ coords,
                                                 const float* __restrict__ W1,
                                                 const float* __restrict__ W2,
                                                 const float* __restrict__ b2, int E) {
    extern __shared__ float sm[];
    unsigned* Wu = (unsigned*)sm;            // [128][68] half2
    unsigned* Xu = (unsigned*)sm + 8704;     // [64][68] half2
    float* b2s   = sm + 13056;               // [128]
    float* sdist = sm + 13184;               // [64]
    int* ss = (int*)(sm + 13248);            // [64]
    int* sr = (int*)(sm + 13312);            // [64]
    const int t = threadIdx.x;

    for (int idx = t; idx < DD * 64; idx += 256) {
        int d = idx >> 6, kk = idx & 63;
        Wu[d * 68 + kk] = f16x2(W2[d * DD + 2 * kk], W2[d * DD + 2 * kk + 1]);
    }
    if (t < DD) b2s[t] = b2[t];

    const int dp = t & 63, q = t >> 6;       // stage1: feature pair x edge quarter
    const float wd0 = W1[(2 * dp) * 257 + 256];
    const float wd1 = W1[(2 * dp + 1) * 257 + 256];
    const int warp = t >> 5, lane = t & 31, g = lane >> 2, tg = lane & 3;
    const int mt = warp >> 1;                // 4 m-tiles of 16 edges
    const int nh = warp & 1;                 // d-half

    const int numTiles = (E + 63) >> 6;
    for (int tile = blockIdx.x; tile < numTiles; tile += gridDim.x) {
        const int e0 = tile << 6;
        __syncthreads();
        if (t < 64) {
            int e = e0 + t;
            int s = 0, r = 0;
            float dist = 0.f;
            if (e < E) {
                s = g_eidx[e];
                r = g_eidx[E + e];
                float dx = coords[s * 3 + 0] - coords[r * 3 + 0];
                float dy = coords[s * 3 + 1] - coords[r * 3 + 1];
                float dz = coords[s * 3 + 2] - coords[r * 3 + 2];
                dist = sqrtf(fmaf(dx, dx, fmaf(dy, dy, dz * dz)));
            }
            ss[t] = s; sr[t] = r; sdist[t] = dist;
        }
        __syncthreads();

        // Stage 1: 16 edges x feature pair (2dp, 2dp+1)
#pragma unroll 4
        for (int e2 = 0; e2 < 16; e2++) {
            int e = q * 16 + e2;
            int s = ss[e], r = sr[e];
            float dist = sdist[e];
            float2 p  = *(const float2*)(g_P + (size_t)s * DD + 2 * dp);
            float2 qq = *(const float2*)(g_Q + (size_t)r * DD + 2 * dp);
            float zx = fast_silu(p.x + qq.x + dist * wd0);
            float zy = fast_silu(p.y + qq.y + dist * wd1);
            Xu[e * 68 + dp] = f16x2(zx, zy);
        }
        __syncthreads();

        // mma: warp computes [16 edges] x [64 d]; K = 128 in 8 k16-steps
        float acc[8][4] = {};
        const int row0 = mt * 16 + g;
#pragma unroll
        for (int ks = 0; ks < 8; ks++) {
            const int kk = ks * 8 + tg;
            unsigned a0 = Xu[row0 * 68 + kk];
            unsigned a1 = Xu[(row0 + 8) * 68 + kk];
            unsigned a2 = Xu[row0 * 68 + kk + 4];
            unsigned a3 = Xu[(row0 + 8) * 68 + kk + 4];
#pragma unroll
            for (int nt = 0; nt < 8; nt++) {
                const int d = nh * 64 + nt * 8 + g;
                unsigned b0 = Wu[d * 68 + kk];
                unsigned b1 = Wu[d * 68 + kk + 4];
                mma_f16(acc[nt], a0, a1, a2, a3, b0, b1);
            }
        }

        // Epilogue: silu + red.v2 scatter
        const bool ok0 = (e0 + row0) < E;
        const bool ok1 = (e0 + row0 + 8) < E;
        const int r0 = sr[row0], r1 = sr[row0 + 8];
#pragma unroll
        for (int nt = 0; nt < 8; nt++) {
            int d = nh * 64 + nt * 8 + 2 * tg;
            float ba = b2s[d], bb = b2s[d + 1];
            if (ok0) {
                float v0 = fast_silu(acc[nt][0] + ba);
                float v1 = fast_silu(acc[nt][1] + bb);
                red_add_v2(g_agg + (size_t)r0 * DD + d, v0, v1);
            }
            if (ok1) {
                float v2 = fast_silu(acc[nt][2] + ba);
                float v3 = fast_silu(acc[nt][3] + bb);
                red_add_v2(g_agg + (size_t)r1 * DD + d, v2, v3);
            }
        }
    }
}

// ---------------------------------------------------------------------------
// Kernel 3: t = silu(U1 @ [h ; agg] + c1), K=256, blockIdx.y = d-half.
// ---------------------------------------------------------------------------
__global__ __launch_bounds__(256) void k_u1(const float* __restrict__ h,
                                            const float* __restrict__ U1,
                                            const float* __restrict__ c1, int N) {
    extern __shared__ float sm[];
    float* Wt = sm;            // [256 k][68 dl]
    float* Xs = sm + 256 * 68; // [128 k][65]
    const int t = threadIdx.x;
    const int half = blockIdx.y;

    for (int idx = t; idx < 64 * 256; idx += 256) {
        int dl = idx >> 8, k = idx & 255;
        Wt[k * 68 + dl] = U1[(size_t)(half * 64 + dl) * 256 + k];
    }
    const int l = t & 31, w = t >> 5;
    const int n0 = blockIdx.x * 64;
    const int og = t >> 5, ng = t & 31;
    ull acc[4][2] = {};

    for (int r = w; r < 64; r += 8) {
        int node = n0 + r;
        for (int k = l; k < DD; k += 32)
            Xs[k * 65 + r] = (node < N) ? h[(size_t)node * DD + k] : 0.f;
    }
    __syncthreads();
#pragma unroll 8
    for (int k = 0; k < DD; k++) {
        const float* wr = Wt + k * 68 + og * 8;
        ulonglong2 wa = *(const ulonglong2*)wr;
        ulonglong2 wb = *(const ulonglong2*)(wr + 4);
        ull wv[4] = {wa.x, wa.y, wb.x, wb.y};
#pragma unroll
        for (int j = 0; j < 2; j++) {
            float x = Xs[k * 65 + ng + 32 * j];
            ull xp = pack2(x, x);
#pragma unroll
            for (int p = 0; p < 4; p++) fma2(acc[p][j], wv[p], xp);
        }
    }
    __syncthreads();

    for (int r = w; r < 64; r += 8) {
        int node = n0 + r;
        for (int k = l; k < DD; k += 32)
            Xs[k * 65 + r] = (node < N) ? g_agg[(size_t)node * DD + k] : 0.f;
    }
    __syncthreads();
#pragma unroll 8
    for (int k = 0; k < DD; k++) {
        const float* wr = Wt + (DD + k) * 68 + og * 8;
        ulonglong2 wa = *(const ulonglong2*)wr;
        ulonglong2 wb = *(const ulonglong2*)(wr + 4);
        ull wv[4] = {wa.x, wa.y, wb.x, wb.y};
#pragma unroll
        for (int j = 0; j < 2; j++) {
            float x = Xs[k * 65 + ng + 32 * j];
            ull xp = pack2(x, x);
#pragma unroll
            for (int p = 0; p < 4; p++) fma2(acc[p][j], wv[p], xp);
        }
    }

#pragma unroll
    for (int j = 0; j < 2; j++) {
        int node = n0 + ng + 32 * j;
        if (node >= N) continue;
        float v[8];
#pragma unroll
        for (int p = 0; p < 4; p++) unpack2(acc[p][j], v[2 * p], v[2 * p + 1]);
        int d0 = half * 64 + og * 8;
        float* dst = g_t + (size_t)node * DD + d0;
#pragma unroll
        for (int i = 0; i < 8; i++)
            dst[i] = fast_silu(v[i] + c1[d0 + i]);
    }
}

// ---------------------------------------------------------------------------
// Kernel 4: out = h + U2 @ t + c2, K=128, blockIdx.y = d-half.
// ---------------------------------------------------------------------------
__global__ __launch_bounds__(256, 3) void k_u2(const float* __restrict__ h,
                                               const float* __restrict__ U2,
                                               const float* __restrict__ c2,
                                               float* __restrict__ out, int N) {
    extern __shared__ float sm[];
    float* Wt = sm;            // [128 k][68 dl]
    float* Xs = sm + 128 * 68; // [128 k][65]
    const int t = threadIdx.x;
    const int half = blockIdx.y;

    for (int idx = t; idx < 64 * DD; idx += 256) {
        int dl = idx >> 7, k = idx & 127;
        Wt[k * 68 + dl] = U2[(size_t)(half * 64 + dl) * DD + k];
    }
    const int l = t & 31, w = t >> 5;
    const int n0 = blockIdx.x * 64;
    for (int r = w; r < 64; r += 8) {
        int node = n0 + r;
        for (int k = l; k < DD; k += 32)
            Xs[k * 65 + r] = (node < N) ? g_t[(size_t)node * DD + k] : 0.f;
    }
    __syncthreads();

    const int og = t >> 5, ng = t & 31;
    ull acc[4][2] = {};
#pragma unroll 8
    for (int k = 0; k < DD; k++) {
        const float* wr = Wt + k * 68 + og * 8;
        ulonglong2 wa = *(const ulonglong2*)wr;
        ulonglong2 wb = *(const ulonglong2*)(wr + 4);
        ull wv[4] = {wa.x, wa.y, wb.x, wb.y};
#pragma unroll
        for (int j = 0; j < 2; j++) {
            float x = Xs[k * 65 + ng + 32 * j];
            ull xp = pack2(x, x);
#pragma unroll
            for (int p = 0; p < 4; p++) fma2(acc[p][j], wv[p], xp);
        }
    }
#pragma unroll
    for (int j = 0; j < 2; j++) {
        int node = n0 + ng + 32 * j;
        if (node >= N) continue;
        float v[8];
#pragma unroll
        for (int p = 0; p < 4; p++) unpack2(acc[p][j], v[2 * p], v[2 * p + 1]);
        int d0 = half * 64 + og * 8;
        const float* hs = h + (size_t)node * DD + d0;
        float* dst = out + (size_t)node * DD + d0;
#pragma unroll
        for (int i = 0; i < 8; i++)
            dst[i] = hs[i] + v[i] + c2[d0 + i];
    }
}

// ---------------------------------------------------------------------------
extern "C" void kernel_launch(void* const* d_in, const int* in_sizes, int n_in,
                              void* d_out, int out_size) {
    const float* h        = (const float*)d_in[0];
    const float* coords   = (const float*)d_in[1];
    const void*  ei       = d_in[2];
    const float* W1       = (const float*)d_in[3];
    const float* b1       = (const float*)d_in[4];
    const float* W2       = (const float*)d_in[5];
    const float* b2       = (const float*)d_in[6];
    const float* U1       = (const float*)d_in[7];
    const float* c1       = (const float*)d_in[8];
    const float* U2       = (const float*)d_in[9];
    const float* c2       = (const float*)d_in[10];
    float* out = (float*)d_out;

    const int N = in_sizes[0] / DD;
    const int E = in_sizes[2] / 2;

    const size_t sm_pq = (128 * 132 + 128 * 65) * sizeof(float);
    const size_t sm_e  = 13376 * sizeof(float); // 52.25 KB
    const size_t sm_u1 = (256 * 68 + 128 * 65) * sizeof(float);
    const size_t sm_u2 = (128 * 68 + 128 * 65) * sizeof(float);

    cudaFuncSetAttribute(k_pq,   cudaFuncAttributeMaxDynamicSharedMemorySize, (int)sm_pq);
    cudaFuncSetAttribute(k_edge, cudaFuncAttributeMaxDynamicSharedMemorySize, (int)sm_e);
    cudaFuncSetAttribute(k_u1,   cudaFuncAttributeMaxDynamicSharedMemorySize, (int)sm_u1);
    cudaFuncSetAttribute(k_u2,   cudaFuncAttributeMaxDynamicSharedMemorySize, (int)sm_u2);

    void* aggPtr = nullptr;
    cudaGetSymbolAddress(&aggPtr, g_agg);
    cudaMemsetAsync(aggPtr, 0, (size_t)N * DD * sizeof(float));

    const int nodeTiles = (N + 63) / 64;
    const int edgeTiles = (E + 63) / 64;
    const int edgeGrid = edgeTiles < 592 ? edgeTiles : 592; // 4 CTAs/SM persistent

    dim3 gPQ(nodeTiles, 2), gU1(nodeTiles, 2), gU2(nodeTiles, 2);

    k_detect<<<1, 32>>>((const unsigned int*)ei);
    k_conv<<<(2 * E + 255) / 256, 256>>>(ei, 2 * E, N);
    k_pq<<<gPQ, 256, sm_pq>>>(h, W1, b1, N);
    k_edge<<<edgeGrid, 256, sm_e>>>(coords, W1, W2, b2, E);
    k_u1<<<gU1, 256, sm_u1>>>(h, U1, c1, N);
    k_u2<<<gU2, 256, sm_u2>>>(h, U2, c2, out, N);
}

// round 8
// speedup vs baseline: 7.1063x; 2.2404x over previous
#include <cuda_runtime.h>
#include <cuda_fp16.h>
#include <math.h>

#define DD 128
#define MAXN 50000
#define MAXE 800000

__device__ unsigned g_Ph[MAXN * 64];   // A @ h_n           (f16x2 pairs)
__device__ unsigned g_Qh[MAXN * 64];   // B @ h_n + b1      (f16x2 pairs)
__device__ float    g_agg[MAXN * DD];  // scatter-add target (fp32)
__device__ unsigned g_th[MAXN * 64];   // silu(U1@[h;agg]+c1) (f16x2 pairs)
__device__ int      g_eidx[2 * MAXE];  // normalized int32 edge index
__device__ int      g_is64;            // dtype probe result

__device__ __forceinline__ float fast_silu(float x) {
    float hx = 0.5f * x, t;
    asm("tanh.approx.f32 %0, %1;" : "=f"(t) : "f"(hx));
    return fmaf(hx, t, hx);
}

__device__ __forceinline__ void red_add_v2(float* p, float a, float b) {
    asm volatile("red.global.add.v2.f32 [%0], {%1,%2};"
                 :: "l"(p), "f"(a), "f"(b) : "memory");
}

// pack (lo, hi) fp32 -> f16x2
__device__ __forceinline__ unsigned f16x2(float lo, float hi) {
    unsigned r;
    asm("cvt.rn.f16x2.f32 %0, %1, %2;" : "=r"(r) : "f"(hi), "f"(lo));
    return r;
}
__device__ __forceinline__ float2 unpackh2(unsigned u) {
    __half2 h = *reinterpret_cast<const __half2*>(&u);
    return __half22float2(h);
}

// m16n8k16 f16 mma: A row-major (16x16), B col-major (16x8), fp32 accum
__device__ __forceinline__ void mma_f16(float* c, unsigned a0, unsigned a1,
                                        unsigned a2, unsigned a3,
                                        unsigned b0, unsigned b1) {
    asm volatile(
        "mma.sync.aligned.m16n8k16.row.col.f32.f16.f16.f32 "
        "{%0,%1,%2,%3}, {%4,%5,%6,%7}, {%8,%9}, {%0,%1,%2,%3};"
        : "+f"(c[0]), "+f"(c[1]), "+f"(c[2]), "+f"(c[3])
        : "r"(a0), "r"(a1), "r"(a2), "r"(a3), "r"(b0), "r"(b1));
}

// ---------------------------------------------------------------------------
// Kernel 0a/0b: edge_index dtype probe + normalize to int32
// ---------------------------------------------------------------------------
__global__ void k_detect(const unsigned int* __restrict__ p) {
    if (threadIdx.x == 0) {
        int is64 = 1;
        for (int i = 0; i < 512; i++)
            if (p[2 * i + 1] != 0u) { is64 = 0; break; }
        g_is64 = is64;
    }
}

__global__ __launch_bounds__(256) void k_conv(const void* __restrict__ ei,
                                              int twoE, int N) {
    int i = blockIdx.x * blockDim.x + threadIdx.x;
    if (i >= twoE) return;
    long long v = g_is64 ? ((const long long*)ei)[i]
                         : (long long)((const int*)ei)[i];
    if (v < 0) v = 0;
    if (v >= N) v = N - 1;
    g_eidx[i] = (int)v;
}

// ---------------------------------------------------------------------------
// Kernel 1: by=0 -> Ph = A @ h (f16x2);  by=1 -> Qh = B @ h + b1 (f16x2)
// fp16 MMA, 64-node tiles, 256 thr, persistent, 4 CTAs/SM.
// ---------------------------------------------------------------------------
__global__ __launch_bounds__(256, 4) void k_pq(const float* __restrict__ h,
                                               const float* __restrict__ W1,
                                               const float* __restrict__ b1, int N) {
    extern __shared__ float sm[];
    unsigned* Wu = (unsigned*)sm;          // [128 d][68] half2 pairs of k
    unsigned* Xu = (unsigned*)sm + 8704;   // [64 n][68]
    const int t = threadIdx.x;
    const int by = blockIdx.y;

    for (int idx = t; idx < DD * 64; idx += 256) {
        int d = idx >> 6, kk = idx & 63;
        const float* wr = W1 + (size_t)d * 257 + by * DD + 2 * kk;
        Wu[d * 68 + kk] = f16x2(wr[0], wr[1]);
    }
    const int dp = t & 63, q = t >> 6;
    const int warp = t >> 5, lane = t & 31, g = lane >> 2, tg = lane & 3;
    const int mt = warp >> 1, nh = warp & 1;
    const int row0 = mt * 16 + g;

    const int numTiles = (N + 63) >> 6;
    for (int tile = blockIdx.x; tile < numTiles; tile += gridDim.x) {
        const int n0 = tile << 6;
        __syncthreads();
#pragma unroll 4
        for (int e2 = 0; e2 < 16; e2++) {
            int row = q * 16 + e2;
            int node = n0 + row;
            unsigned v = 0;
            if (node < N) {
                float2 hv = *(const float2*)(h + (size_t)node * DD + 2 * dp);
                v = f16x2(hv.x, hv.y);
            }
            Xu[row * 68 + dp] = v;
        }
        __syncthreads();

        float acc[8][4] = {};
#pragma unroll
        for (int ks = 0; ks < 8; ks++) {
            const int kk = ks * 8 + tg;
            unsigned a0 = Xu[row0 * 68 + kk];
            unsigned a1 = Xu[(row0 + 8) * 68 + kk];
            unsigned a2 = Xu[row0 * 68 + kk + 4];
            unsigned a3 = Xu[(row0 + 8) * 68 + kk + 4];
#pragma unroll
            for (int nt = 0; nt < 8; nt++) {
                const int d = nh * 64 + nt * 8 + g;
                mma_f16(acc[nt], a0, a1, a2, a3, Wu[d * 68 + kk], Wu[d * 68 + kk + 4]);
            }
        }

        const int node0 = n0 + row0, node1 = node0 + 8;
        unsigned* dstArr = by ? g_Qh : g_Ph;
#pragma unroll
        for (int nt = 0; nt < 8; nt++) {
            int d = nh * 64 + nt * 8 + 2 * tg;
            float ba = 0.f, bb = 0.f;
            if (by) { ba = b1[d]; bb = b1[d + 1]; }
            if (node0 < N)
                dstArr[(size_t)node0 * 64 + (d >> 1)] = f16x2(acc[nt][0] + ba, acc[nt][1] + bb);
            if (node1 < N)
                dstArr[(size_t)node1 * 64 + (d >> 1)] = f16x2(acc[nt][2] + ba, acc[nt][3] + bb);
        }
    }
}

// ---------------------------------------------------------------------------
// Kernel 2 (edge): fp16 MMA, 64-edge tiles, 256 thr, 4 CTAs/SM.
// Stage1 gathers f16x2 P/Q rows (half the bytes of fp32).
// ---------------------------------------------------------------------------
__global__ __launch_bounds__(256, 4) void k_edge(const float* __restrict__ coords,
                                                 const float* __restrict__ W1,
                                                 const float* __restrict__ W2,
                                                 const float* __restrict__ b2, int E) {
    extern __shared__ float sm[];
    unsigned* Wu = (unsigned*)sm;            // [128][68] half2
    unsigned* Xu = (unsigned*)sm + 8704;     // [64][68] half2
    float* b2s   = sm + 13056;               // [128]
    float* sdist = sm + 13184;               // [64]
    int* ss = (int*)(sm + 13248);            // [64]
    int* sr = (int*)(sm + 13312);            // [64]
    const int t = threadIdx.x;

    for (int idx = t; idx < DD * 64; idx += 256) {
        int d = idx >> 6, kk = idx & 63;
        Wu[d * 68 + kk] = f16x2(W2[d * DD + 2 * kk], W2[d * DD + 2 * kk + 1]);
    }
    if (t < DD) b2s[t] = b2[t];

    const int dp = t & 63, q = t >> 6;
    const float wd0 = W1[(2 * dp) * 257 + 256];
    const float wd1 = W1[(2 * dp + 1) * 257 + 256];
    const int warp = t >> 5, lane = t & 31, g = lane >> 2, tg = lane & 3;
    const int mt = warp >> 1, nh = warp & 1;
    const int row0 = mt * 16 + g;

    const int numTiles = (E + 63) >> 6;
    for (int tile = blockIdx.x; tile < numTiles; tile += gridDim.x) {
        const int e0 = tile << 6;
        __syncthreads();
        if (t < 64) {
            int e = e0 + t;
            int s = 0, r = 0;
            float dist = 0.f;
            if (e < E) {
                s = g_eidx[e];
                r = g_eidx[E + e];
                float dx = coords[s * 3 + 0] - coords[r * 3 + 0];
                float dy = coords[s * 3 + 1] - coords[r * 3 + 1];
                float dz = coords[s * 3 + 2] - coords[r * 3 + 2];
                dist = sqrtf(fmaf(dx, dx, fmaf(dy, dy, dz * dz)));
            }
            ss[t] = s; sr[t] = r; sdist[t] = dist;
        }
        __syncthreads();

        // Stage 1: 16 edges x feature pair (2dp, 2dp+1), f16x2 gathers
#pragma unroll 4
        for (int e2 = 0; e2 < 16; e2++) {
            int e = q * 16 + e2;
            int s = ss[e], r = sr[e];
            float dist = sdist[e];
            float2 p  = unpackh2(g_Ph[(size_t)s * 64 + dp]);
            float2 qq = unpackh2(g_Qh[(size_t)r * 64 + dp]);
            float zx = fast_silu(p.x + qq.x + dist * wd0);
            float zy = fast_silu(p.y + qq.y + dist * wd1);
            Xu[e * 68 + dp] = f16x2(zx, zy);
        }
        __syncthreads();

        float acc[8][4] = {};
#pragma unroll
        for (int ks = 0; ks < 8; ks++) {
            const int kk = ks * 8 + tg;
            unsigned a0 = Xu[row0 * 68 + kk];
            unsigned a1 = Xu[(row0 + 8) * 68 + kk];
            unsigned a2 = Xu[row0 * 68 + kk + 4];
            unsigned a3 = Xu[(row0 + 8) * 68 + kk + 4];
#pragma unroll
            for (int nt = 0; nt < 8; nt++) {
                const int d = nh * 64 + nt * 8 + g;
                mma_f16(acc[nt], a0, a1, a2, a3, Wu[d * 68 + kk], Wu[d * 68 + kk + 4]);
            }
        }

        const bool ok0 = (e0 + row0) < E;
        const bool ok1 = (e0 + row0 + 8) < E;
        const int r0 = sr[row0], r1 = sr[row0 + 8];
#pragma unroll
        for (int nt = 0; nt < 8; nt++) {
            int d = nh * 64 + nt * 8 + 2 * tg;
            float ba = b2s[d], bb = b2s[d + 1];
            if (ok0) {
                float v0 = fast_silu(acc[nt][0] + ba);
                float v1 = fast_silu(acc[nt][1] + bb);
                red_add_v2(g_agg + (size_t)r0 * DD + d, v0, v1);
            }
            if (ok1) {
                float v2 = fast_silu(acc[nt][2] + ba);
                float v3 = fast_silu(acc[nt][3] + bb);
                red_add_v2(g_agg + (size_t)r1 * DD + d, v2, v3);
            }
        }
    }
}

// ---------------------------------------------------------------------------
// Kernel 3: th = f16x2(silu(U1 @ [h ; agg] + c1)), K=256.
// fp16 MMA, stride 140 (conflict-free: 12g mod 32 distinct), 2 CTAs/SM.
// ---------------------------------------------------------------------------
__global__ __launch_bounds__(256, 2) void k_u1(const float* __restrict__ h,
                                               const float* __restrict__ U1,
                                               const float* __restrict__ c1, int N) {
    extern __shared__ float sm[];
    unsigned* Wu = (unsigned*)sm;            // [128 d][140] half2 pairs (128 used)
    unsigned* Xu = (unsigned*)sm + 128 * 140;// [64 n][140]
    const int t = threadIdx.x;

    for (int idx = t; idx < DD * 128; idx += 256) {
        int d = idx >> 7, kk = idx & 127;
        Wu[d * 140 + kk] = f16x2(U1[(size_t)d * 256 + 2 * kk], U1[(size_t)d * 256 + 2 * kk + 1]);
    }
    const int dp = t & 63, q = t >> 6;
    const int warp = t >> 5, lane = t & 31, g = lane >> 2, tg = lane & 3;
    const int mt = warp >> 1, nh = warp & 1;
    const int row0 = mt * 16 + g;

    const int numTiles = (N + 63) >> 6;
    for (int tile = blockIdx.x; tile < numTiles; tile += gridDim.x) {
        const int n0 = tile << 6;
        __syncthreads();
#pragma unroll 4
        for (int e2 = 0; e2 < 16; e2++) {
            int row = q * 16 + e2;
            int node = n0 + row;
            unsigned vh = 0, va = 0;
            if (node < N) {
                float2 hv = *(const float2*)(h + (size_t)node * DD + 2 * dp);
                float2 av = *(const float2*)(g_agg + (size_t)node * DD + 2 * dp);
                vh = f16x2(hv.x, hv.y);
                va = f16x2(av.x, av.y);
            }
            Xu[row * 140 + dp] = vh;
            Xu[row * 140 + 64 + dp] = va;
        }
        __syncthreads();

        float acc[8][4] = {};
#pragma unroll
        for (int ks = 0; ks < 16; ks++) {
            const int kk = ks * 8 + tg;
            unsigned a0 = Xu[row0 * 140 + kk];
            unsigned a1 = Xu[(row0 + 8) * 140 + kk];
            unsigned a2 = Xu[row0 * 140 + kk + 4];
            unsigned a3 = Xu[(row0 + 8) * 140 + kk + 4];
#pragma unroll
            for (int nt = 0; nt < 8; nt++) {
                const int d = nh * 64 + nt * 8 + g;
                mma_f16(acc[nt], a0, a1, a2, a3, Wu[d * 140 + kk], Wu[d * 140 + kk + 4]);
            }
        }

        const int node0 = n0 + row0, node1 = node0 + 8;
#pragma unroll
        for (int nt = 0; nt < 8; nt++) {
            int d = nh * 64 + nt * 8 + 2 * tg;
            float ca = c1[d], cb = c1[d + 1];
            if (node0 < N)
                g_th[(size_t)node0 * 64 + (d >> 1)] =
                    f16x2(fast_silu(acc[nt][0] + ca), fast_silu(acc[nt][1] + cb));
            if (node1 < N)
                g_th[(size_t)node1 * 64 + (d >> 1)] =
                    f16x2(fast_silu(acc[nt][2] + ca), fast_silu(acc[nt][3] + cb));
        }
    }
}

// ---------------------------------------------------------------------------
// Kernel 4: out = h + U2 @ t + c2, K=128. fp16 MMA, 4 CTAs/SM.
// X comes from g_th (already f16x2 — direct copy).
// ---------------------------------------------------------------------------
__global__ __launch_bounds__(256, 4) void k_u2(const float* __restrict__ h,
                                               const float* __restrict__ U2,
                                               const float* __restrict__ c2,
                                               float* __restrict__ out, int N) {
    extern __shared__ float sm[];
    unsigned* Wu = (unsigned*)sm;          // [128][68]
    unsigned* Xu = (unsigned*)sm + 8704;   // [64][68]
    const int t = threadIdx.x;

    for (int idx = t; idx < DD * 64; idx += 256) {
        int d = idx >> 6, kk = idx & 63;
        Wu[d * 68 + kk] = f16x2(U2[(size_t)d * DD + 2 * kk], U2[(size_t)d * DD + 2 * kk + 1]);
    }
    const int dp = t & 63, q = t >> 6;
    const int warp = t >> 5, lane = t & 31, g = lane >> 2, tg = lane & 3;
    const int mt = warp >> 1, nh = warp & 1;
    const int row0 = mt * 16 + g;

    const int numTiles = (N + 63) >> 6;
    for (int tile = blockIdx.x; tile < numTiles; tile += gridDim.x) {
        const int n0 = tile << 6;
        __syncthreads();
#pragma unroll 4
        for (int e2 = 0; e2 < 16; e2++) {
            int row = q * 16 + e2;
            int node = n0 + row;
            Xu[row * 68 + dp] = (node < N) ? g_th[(size_t)node * 64 + dp] : 0u;
        }
        __syncthreads();

        float acc[8][4] = {};
#pragma unroll
        for (int ks = 0; ks < 8; ks++) {
            const int kk = ks * 8 + tg;
            unsigned a0 = Xu[row0 * 68 + kk];
            unsigned a1 = Xu[(row0 + 8) * 68 + kk];
            unsigned a2 = Xu[row0 * 68 + kk + 4];
            unsigned a3 = Xu[(row0 + 8) * 68 + kk + 4];
#pragma unroll
            for (int nt = 0; nt < 8; nt++) {
                const int d = nh * 64 + nt * 8 + g;
                mma_f16(acc[nt], a0, a1, a2, a3, Wu[d * 68 + kk], Wu[d * 68 + kk + 4]);
            }
        }

        const int node0 = n0 + row0, node1 = node0 + 8;
#pragma unroll
        for (int nt = 0; nt < 8; nt++) {
            int d = nh * 64 + nt * 8 + 2 * tg;
            float ca = c2[d], cb = c2[d + 1];
            if (node0 < N) {
                float2 hv = *(const float2*)(h + (size_t)node0 * DD + d);
                *(float2*)(out + (size_t)node0 * DD + d) =
                    make_float2(hv.x + acc[nt][0] + ca, hv.y + acc[nt][1] + cb);
            }
            if (node1 < N) {
                float2 hv = *(const float2*)(h + (size_t)node1 * DD + d);
                *(float2*)(out + (size_t)node1 * DD + d) =
                    make_float2(hv.x + acc[nt][2] + ca, hv.y + acc[nt][3] + cb);
            }
        }
    }
}

// ---------------------------------------------------------------------------
extern "C" void kernel_launch(void* const* d_in, const int* in_sizes, int n_in,
                              void* d_out, int out_size) {
    const float* h        = (const float*)d_in[0];
    const float* coords   = (const float*)d_in[1];
    const void*  ei       = d_in[2];
    const float* W1       = (const float*)d_in[3];
    const float* b1       = (const float*)d_in[4];
    const float* W2       = (const float*)d_in[5];
    const float* b2       = (const float*)d_in[6];
    const float* U1       = (const float*)d_in[7];
    const float* c1       = (const float*)d_in[8];
    const float* U2       = (const float*)d_in[9];
    const float* c2       = (const float*)d_in[10];
    float* out = (float*)d_out;

    const int N = in_sizes[0] / DD;
    const int E = in_sizes[2] / 2;

    const size_t sm_pq = (8704 + 64 * 68) * sizeof(unsigned);           // 52.25KB-ish
    const size_t sm_e  = 13376 * sizeof(float);                          // 52.25 KB
    const size_t sm_u1 = (128 * 140 + 64 * 140) * sizeof(unsigned);      // 105 KB
    const size_t sm_u2 = (8704 + 64 * 68) * sizeof(unsigned);

    cudaFuncSetAttribute(k_pq,   cudaFuncAttributeMaxDynamicSharedMemorySize, (int)sm_pq);
    cudaFuncSetAttribute(k_edge, cudaFuncAttributeMaxDynamicSharedMemorySize, (int)sm_e);
    cudaFuncSetAttribute(k_u1,   cudaFuncAttributeMaxDynamicSharedMemorySize, (int)sm_u1);
    cudaFuncSetAttribute(k_u2,   cudaFuncAttributeMaxDynamicSharedMemorySize, (int)sm_u2);

    void* aggPtr = nullptr;
    cudaGetSymbolAddress(&aggPtr, g_agg);
    cudaMemsetAsync(aggPtr, 0, (size_t)N * DD * sizeof(float));

    const int nodeTiles = (N + 63) / 64;
    const int edgeTiles = (E + 63) / 64;
    const int edgeGrid = edgeTiles < 592 ? edgeTiles : 592;
    const int pqGrid   = nodeTiles < 296 ? nodeTiles : 296;  // x2 via grid.y -> 4/SM
    const int u1Grid   = nodeTiles < 296 ? nodeTiles : 296;  // 2/SM
    const int u2Grid   = nodeTiles < 592 ? nodeTiles : 592;  // 4/SM

    dim3 gPQ(pqGrid, 2);

    k_detect<<<1, 32>>>((const unsigned int*)ei);
    k_conv<<<(2 * E + 255) / 256, 256>>>(ei, 2 * E, N);
    k_pq<<<gPQ, 256, sm_pq>>>(h, W1, b1, N);
    k_edge<<<edgeGrid, 256, sm_e>>>(coords, W1, W2, b2, E);
    k_u1<<<u1Grid, 256, sm_u1>>>(h, U1, c1, N);
    k_u2<<<u2Grid, 256, sm_u2>>>(h, U2, c2, out, N);
}